// round 1
// baseline (speedup 1.0000x reference)
#include <cuda_runtime.h>
#include <math.h>

// Problem constants (fixed by reference setup_inputs)
#define Bb   32
#define Ss   512
#define Hh   512
#define Nn   (Bb*Ss)        // 16384 tokens
#define CN   4096           // 8 gates * H, interleaved c = k*8 + g
#define KX   2048           // [h | hb | ha | sw_h]
#define NLAYERS 4

// ---------------- device scratch (no allocations allowed) ----------------
__device__ float g_X    [(size_t)Nn*KX];   // 134 MB  GEMM input per layer
__device__ float g_Zc   [(size_t)Nn*CN];   // 268 MB  emb@Wi + b (layer-invariant)
__device__ float g_Wall [(size_t)KX*CN];   // 33 MB   [Wx;Wh;Ws] gate-interleaved
__device__ float g_WiAll[(size_t)Hh*CN];   // 8 MB    Wi gate-interleaved
__device__ float g_emb  [(size_t)Nn*Hh];
__device__ float g_h    [(size_t)Nn*Hh];
__device__ float g_c    [(size_t)Nn*Hh];
__device__ float g_cb   [(size_t)Nn*Hh];
__device__ float g_ca   [(size_t)Nn*Hh];
__device__ float g_swc  [(size_t)Nn*Hh];
__device__ float g_gf   [(size_t)Nn*Hh];
__device__ float g_zd   [Bb*CN];
__device__ float g_dh   [2][Bb*Hh];
__device__ float g_dc   [2][Bb*Hh];
__device__ float g_comb [Bb*Hh];
__device__ float g_gd   [Bb*Hh];
__device__ float g_go   [Bb*Hh];
__device__ float g_gfx  [Bb*Hh];

__device__ __forceinline__ float sigm(float x) { return 1.f/(1.f+__expf(-x)); }

// ---------------- weight rearrangement ----------------
// Wall[j][c], c = k*8+g : rows 0..511 = Wx[g][j][k], 512..1535 = Wh[g][j-512][k],
// 1536..2047 = Ws[g][j-1536][k]
__global__ void k_prepw(const float* __restrict__ Wx, const float* __restrict__ Wh,
                        const float* __restrict__ Ws) {
    int idx = blockIdx.x*256 + threadIdx.x;          // < 2048*4096
    int c = idx & 4095, j = idx >> 12;
    int g = c & 7, k = c >> 3;
    float v;
    if (j < 512)        v = Wx[((size_t)((g<<9)  + j       ))*512 + k];
    else if (j < 1536)  v = Wh[((size_t)((g<<10) + (j-512) ))*512 + k];
    else                v = Ws[((size_t)((g<<9)  + (j-1536)))*512 + k];
    g_Wall[idx] = v;
}

__global__ void k_prepwi(const float* __restrict__ Wi) {
    int idx = blockIdx.x*256 + threadIdx.x;          // < 512*4096
    int c = idx & 4095, j = idx >> 12;
    int g = c & 7, k = c >> 3;
    g_WiAll[idx] = Wi[((size_t)((g<<9) + j))*512 + k];
}

// ---------------- init: mask inputs ----------------
__global__ void k_init(const float* __restrict__ word, const float* __restrict__ ih,
                       const float* __restrict__ icc, const int* __restrict__ mask) {
    int n = blockIdx.x, k = threadIdx.x;
    float m = (float)mask[n];
    size_t i = ((size_t)n << 9) + k;
    g_emb[i] = word[i]*m;
    g_h[i]   = ih[i]*m;
    g_c[i]   = icc[i]*m;
}

// mode 0: mean(h)->comb   1: mean(h)->dh[0]   2: mean(c)->dc[0]
__global__ void k_mean(int mode) {
    int b = blockIdx.x, k = threadIdx.x;
    const float* x = (mode == 2) ? g_c : g_h;
    float s = 0.f;
    for (int t = 0; t < Ss; t++) s += x[(((size_t)(b<<9)) + t)*512 + k];
    s *= (1.f/512.f);
    int o = (b<<9) + k;
    if (mode == 0)      g_comb[o]  = s;
    else if (mode == 1) g_dh[0][o] = s;
    else                g_dc[0][o] = s;
}

// small per-batch GEMMs: gd, go, gfx, zd[g]
__global__ void k_small(const float* __restrict__ gW, const float* __restrict__ gb,
                        const float* __restrict__ Wd, int cur) {
    int t = blockIdx.y;
    int idx = blockIdx.x*256 + threadIdx.x;          // 0..16383 = (b,k)
    int b = idx >> 9, k = idx & 511;
    const float* dh = g_dh[cur] + (b<<9);
    float s = 0.f;
    if (t <= 1) {
        const float* W1 = gW + (size_t)(t*2  )*262144;
        const float* W2 = gW + (size_t)(t*2+1)*262144;
        const float* cm = g_comb + (b<<9);
        for (int j = 0; j < 512; j++)
            s = fmaf(dh[j], W1[j*512+k], fmaf(cm[j], W2[j*512+k], s));
        float v = sigm(s + gb[t*512 + k]);
        if (t == 0) g_gd[idx] = v; else g_go[idx] = v;
    } else if (t == 2) {
        const float* W = gW + (size_t)4*262144;      // gWxf
        for (int j = 0; j < 512; j++) s = fmaf(dh[j], W[j*512+k], s);
        g_gfx[idx] = s;
    } else {
        int g = t - 3;
        const float* W = Wd + (size_t)g*262144;
        for (int j = 0; j < 512; j++) s = fmaf(dh[j], W[j*512+k], s);
        g_zd[(b<<12) + (k<<3) + g] = s;
    }
}

// softmax over S+1 entries per (b,k) + new dummies
__global__ void k_soft(int cur) {
    int b = blockIdx.x, k = threadIdx.x;
    int bk = (b<<9) + k;
    float den = __expf(g_gd[bk] - 1.f);              // shift by 1 (all scores <= 1)
    float num = den * g_dc[cur][bk];
    const float* gf = g_gf + (size_t)b*Ss*Hh + k;
    const float* cp = g_c  + (size_t)b*Ss*Hh + k;
    for (int s = 0; s < Ss; s++) {
        float w = __expf(gf[s*512] - 1.f);
        num = fmaf(w, cp[s*512], num);
        den += w;
    }
    float dcn = num/den;
    g_dc[cur^1][bk] = dcn;
    g_dh[cur^1][bk] = g_go[bk]*tanhf(dcn);
}

// X = [h | hb | ha | sw_h]; also cb, ca, swc
__global__ void k_build(const int* __restrict__ pos) {
    int n = blockIdx.x, k = threadIdx.x;
    int b = n >> 9, s = n & 511;
    size_t base = ((size_t)n << 9) + k;
    float hv = g_h[base];
    float hb = (s >= 1 ? g_h[base-512] : 0.f) + (s >= 2 ? g_h[base-1024] : 0.f);
    float ha = (s <= 510 ? g_h[base+512] : 0.f) + (s <= 509 ? g_h[base+1024] : 0.f);
    int p = pos[n];
    float sh = 0.f, sc = 0.f;
    if (p > 0) {
        size_t pb = ((size_t)((b<<9) + p - 1) << 9) + k;
        sh = g_h[pb]; sc = g_c[pb];
    }
    size_t xb = ((size_t)n << 11) + k;
    g_X[xb] = hv; g_X[xb+512] = hb; g_X[xb+1024] = ha; g_X[xb+1536] = sh;
    g_cb[base]  = (s >= 1 ? g_c[base-512] : 0.f) + (s >= 2 ? g_c[base-1024] : 0.f);
    g_ca[base]  = (s <= 510 ? g_c[base+512] : 0.f) + (s <= 509 ? g_c[base+1024] : 0.f);
    g_swc[base] = sc;
}

// ---------------- SGEMM core: 128x128 tile, BK=16, 8x8 per thread ----------------
__device__ __forceinline__ void gemm_mainloop(
    const float* __restrict__ A, const float* __restrict__ Bm,
    int lda, int ldb, int K, int n0, int c0,
    float (&acc)[8][8], float* As, float* Bs)
{
    const int tid = threadIdx.x;
    const int tx = tid & 15, ty = tid >> 4;
    for (int kt = 0; kt < K; kt += 16) {
        #pragma unroll
        for (int l = 0; l < 2; l++) {
            int q = tid + l*256;                 // 512 float4 of A (128 rows x 16 k)
            int row = q >> 2;
            int kq  = (q & 3) << 2;
            const float4 v = *(const float4*)(A + (size_t)(n0+row)*lda + (kt+kq));
            As[(kq+0)*128 + row] = v.x;
            As[(kq+1)*128 + row] = v.y;
            As[(kq+2)*128 + row] = v.z;
            As[(kq+3)*128 + row] = v.w;
        }
        #pragma unroll
        for (int l = 0; l < 2; l++) {
            int q = tid + l*256;                 // 512 float4 of B (16 rows x 128 c)
            int row = q >> 5;
            int c4  = (q & 31) << 2;
            *(float4*)(Bs + row*128 + c4) =
                *(const float4*)(Bm + (size_t)(kt+row)*ldb + c0 + c4);
        }
        __syncthreads();
        #pragma unroll
        for (int kk = 0; kk < 16; kk++) {
            float ra[8], rb[8];
            *(float4*)&ra[0] = *(const float4*)(As + kk*128 + ty*8);
            *(float4*)&ra[4] = *(const float4*)(As + kk*128 + ty*8 + 4);
            *(float4*)&rb[0] = *(const float4*)(Bs + kk*128 + tx*8);
            *(float4*)&rb[4] = *(const float4*)(Bs + kk*128 + tx*8 + 4);
            #pragma unroll
            for (int i = 0; i < 8; i++)
                #pragma unroll
                for (int j = 0; j < 8; j++)
                    acc[i][j] = fmaf(ra[i], rb[j], acc[i][j]);
        }
        __syncthreads();
    }
}

// Zc = emb @ WiAll + bias (gate-interleaved)
__global__ void __launch_bounds__(256) k_gemm_zc(const float* __restrict__ bias) {
    __shared__ __align__(16) float As[16*128];
    __shared__ __align__(16) float Bs[16*128];
    float acc[8][8] = {};
    int n0 = blockIdx.y*128, c0 = blockIdx.x*128;
    gemm_mainloop(g_emb, g_WiAll, 512, CN, 512, n0, c0, acc, As, Bs);
    int tx = threadIdx.x & 15, ty = threadIdx.x >> 4;
    #pragma unroll
    for (int i = 0; i < 8; i++) {
        int n = n0 + ty*8 + i;
        #pragma unroll
        for (int j = 0; j < 8; j++) {
            int cc = c0 + tx*8 + j;
            g_Zc[(size_t)n*CN + cc] = acc[i][j] + bias[(cc & 7)*Hh + (cc >> 3)];
        }
    }
}

// gf = sigmoid(h @ gWhf + gfx + gbf) + mask_score
__global__ void __launch_bounds__(256) k_gemm_gf(const float* __restrict__ gWhf,
                                                 const float* __restrict__ gbf,
                                                 const int* __restrict__ mask) {
    __shared__ __align__(16) float As[16*128];
    __shared__ __align__(16) float Bs[16*128];
    float acc[8][8] = {};
    int n0 = blockIdx.y*128, c0 = blockIdx.x*128;
    gemm_mainloop(g_h, gWhf, 512, 512, 512, n0, c0, acc, As, Bs);
    int tx = threadIdx.x & 15, ty = threadIdx.x >> 4;
    #pragma unroll
    for (int i = 0; i < 8; i++) {
        int n = n0 + ty*8 + i;
        int b = n >> 9;
        float ms = mask[n] ? 0.f : -1e25f;
        #pragma unroll
        for (int j = 0; j < 8; j++) {
            int cc = c0 + tx*8 + j;
            float v = sigm(acc[i][j] + g_gfx[(b<<9)+cc] + gbf[cc]) + ms;
            g_gf[((size_t)n<<9) + cc] = v;
        }
    }
}

// big GEMM + fused SLSTM epilogue. Columns are gate-interleaved: each thread's
// 8 contiguous columns are the 8 gates of ONE output unit kout.
__global__ void __launch_bounds__(256) k_gemm_big(const int* __restrict__ mask,
                                                  float* __restrict__ out,
                                                  int cur, int last) {
    __shared__ __align__(16) float As[16*128];
    __shared__ __align__(16) float Bs[16*128];
    float acc[8][8] = {};
    int n0 = blockIdx.y*128, c0 = blockIdx.x*128;
    gemm_mainloop(g_X, g_Wall, KX, CN, KX, n0, c0, acc, As, Bs);
    int tx = threadIdx.x & 15, ty = threadIdx.x >> 4;
    int cbase = c0 + tx*8;
    int kout = cbase >> 3;
    const float* dc_old = g_dc[cur];
    float* hout = last ? out : g_h;
    #pragma unroll
    for (int i = 0; i < 8; i++) {
        int n = n0 + ty*8 + i;
        int b = n >> 9;
        size_t zoff = (size_t)n*CN + cbase;
        float z[8];
        #pragma unroll
        for (int j = 0; j < 8; j++)
            z[j] = acc[i][j] + g_Zc[zoff + j] + g_zd[(b<<12) + cbase + j];
        float e[6], ssum = 0.f;
        #pragma unroll
        for (int j = 0; j < 6; j++) { e[j] = __expf(sigm(z[j])); ssum += e[j]; }
        float inv = 1.f/ssum;
        float o = sigm(z[6]);
        float u = tanhf(z[7]);
        size_t idx = ((size_t)n << 9) + kout;
        float cn = (e[0]*g_cb[idx] + e[1]*g_ca[idx] + e[2]*g_c[idx]
                  + e[3]*dc_old[(b<<9)+kout] + e[4]*g_swc[idx] + e[5]*u) * inv;
        float m = (float)mask[n];
        cn *= m;
        hout[idx] = o * tanhf(cn) * m;
        g_c[idx] = cn;
    }
}

// ---------------- host ----------------
extern "C" void kernel_launch(void* const* d_in, const int* in_sizes, int n_in,
                              void* d_out, int out_size) {
    const float* word = (const float*)d_in[0];
    const float* ih   = (const float*)d_in[1];
    const float* icc  = (const float*)d_in[2];
    const float* Wx   = (const float*)d_in[3];
    const float* Wh   = (const float*)d_in[4];
    const float* Wi   = (const float*)d_in[5];
    const float* Wd   = (const float*)d_in[6];
    const float* Ws   = (const float*)d_in[7];
    const float* bias = (const float*)d_in[8];
    const float* gW   = (const float*)d_in[9];
    const float* gb   = (const float*)d_in[10];
    const int*   pos  = (const int*)d_in[11];
    const int*   mask = (const int*)d_in[12];
    float* out = (float*)d_out;

    k_prepw <<<(KX*CN)/256, 256>>>(Wx, Wh, Ws);
    k_prepwi<<<(Hh*CN)/256, 256>>>(Wi);
    k_init  <<<Nn, 512>>>(word, ih, icc, mask);
    k_mean  <<<Bb, 512>>>(1);
    k_mean  <<<Bb, 512>>>(2);

    dim3 gbig(CN/128, Nn/128);   // (32, 128)
    k_gemm_zc<<<gbig, 256>>>(bias);

    int cur = 0;
    for (int layer = 0; layer < NLAYERS; layer++) {
        k_mean <<<Bb, 512>>>(0);
        k_small<<<dim3(64, 11), 256>>>(gW, gb, Wd, cur);
        dim3 ggf(Hh/128, Nn/128);  // (4, 128)
        k_gemm_gf<<<ggf, 256>>>(gW + (size_t)5*262144, gb + 1024, mask);
        k_soft <<<Bb, 512>>>(cur);
        k_build<<<Nn, 512>>>(pos);
        k_gemm_big<<<gbig, 256>>>(mask, out, cur, layer == NLAYERS-1);
        cur ^= 1;
    }
}

// round 10
// speedup vs baseline: 1.6693x; 1.6693x over previous
#include <cuda_runtime.h>
#include <cuda_fp16.h>
#include <math.h>
#include <cstdint>

// Problem constants (fixed by reference setup_inputs)
#define Bb   32
#define Ss   512
#define Hh   512
#define Nn   (Bb*Ss)        // 16384 tokens
#define CN   4096           // 8 gates * H, interleaved c = k*8 + g
#define KXT  2560           // [h | hb | ha | sw_h | emb]
#define NLAYERS 4

// HMMA GEMM tiling: 128x128 tile, 256 threads, BK=32, split-fp16 3-term
#define BM 128
#define BN 128
#define BK 32
#define AROW 40                        // BK + 8 pad (halves); 80 bytes/row
#define AH_OFF 0
#define AL_OFF 10240                   // 128*40*2
#define BH_OFF 20480
#define BL_OFF 30720
#define STAGE_BYTES 40960
#define SMEM_BYTES (3*STAGE_BYTES)     // 122880; epilogue zs 128*132*4=67584 fits

// ---------------- device scratch ----------------
__device__ __half g_XH [(size_t)Nn*KXT];   // A hi plane
__device__ __half g_XL [(size_t)Nn*KXT];   // A lo plane
__device__ __half g_WH [(size_t)CN*KXT];   // B hi plane [c][j]
__device__ __half g_WL [(size_t)CN*KXT];   // B lo plane
__device__ __half g_GH [(size_t)Hh*Hh];    // gWhf hi [c][j]
__device__ __half g_GL [(size_t)Hh*Hh];    // gWhf lo
__device__ __half g_hH [(size_t)Nn*Hh];    // h hi (gf GEMM A)
__device__ __half g_hL [(size_t)Nn*Hh];    // h lo
__device__ float g_h  [(size_t)Nn*Hh];
__device__ float g_c  [(size_t)Nn*Hh];
__device__ float g_cb [(size_t)Nn*Hh];
__device__ float g_ca [(size_t)Nn*Hh];
__device__ float g_swc[(size_t)Nn*Hh];
__device__ float g_gf [(size_t)Nn*Hh];
__device__ float g_zd [Bb*CN];
__device__ float g_dh [2][Bb*Hh];
__device__ float g_dc [2][Bb*Hh];
__device__ float g_comb[Bb*Hh];
__device__ float g_gd [Bb*Hh];
__device__ float g_go [Bb*Hh];
__device__ float g_gfx[Bb*Hh];

__device__ __forceinline__ float sigm(float x) { return 1.f/(1.f+__expf(-x)); }
__device__ __forceinline__ void split2h(float v, __half& hi, __half& lo) {
    hi = __float2half_rn(v);
    lo = __float2half_rn(v - __half2float(hi));
}

__device__ __forceinline__ uint32_t smem_u32(const void* p) {
    uint32_t a;
    asm("{ .reg .u64 t; cvta.to.shared.u64 t, %1; cvt.u32.u64 %0, t; }" : "=r"(a) : "l"(p));
    return a;
}
__device__ __forceinline__ void mma16816(float* c, const uint32_t* a, uint32_t b0, uint32_t b1) {
    asm volatile("mma.sync.aligned.m16n8k16.row.col.f32.f16.f16.f32 "
        "{%0,%1,%2,%3},{%4,%5,%6,%7},{%8,%9},{%0,%1,%2,%3};"
        : "+f"(c[0]), "+f"(c[1]), "+f"(c[2]), "+f"(c[3])
        : "r"(a[0]), "r"(a[1]), "r"(a[2]), "r"(a[3]), "r"(b0), "r"(b1));
}
#define LDSM_X4(r, addr) \
    asm volatile("ldmatrix.sync.aligned.m8n8.x4.shared.b16 {%0,%1,%2,%3},[%4];" \
        : "=r"((r)[0]), "=r"((r)[1]), "=r"((r)[2]), "=r"((r)[3]) : "r"(addr))
#define CP_ASYNC(dst, src) \
    asm volatile("cp.async.cg.shared.global [%0],[%1],16;" :: "r"(dst), "l"(src))
#define CP_COMMIT() asm volatile("cp.async.commit_group;")

// ---------------- split-fp16 HMMA mainloop: C[128x128], 3-term ----------------
template<int KCHUNKS>
__device__ __forceinline__ void hmma_mainloop(
    const __half* __restrict__ AHp, const __half* __restrict__ ALp, int lda,
    const __half* __restrict__ BHp, const __half* __restrict__ BLp, int ldb,
    int n0, int c0, char* smem, float acc[2][8][4])
{
    const int tid = threadIdx.x, lane = tid & 31, wid = tid >> 5;
    const int wm = wid >> 1, wn = wid & 1;          // 4x2 warps, warp tile 32x64
    const uint32_t sb = smem_u32(smem);

    const uint32_t a_off0 = (uint32_t)(((wm*32 + (lane & 15))*AROW + (lane >> 4)*8) * 2);
    const uint32_t a_off1 = a_off0 + 16*AROW*2;
    const uint32_t b_off  = (uint32_t)(((wn*64 + ((lane >> 4) << 3) + (lane & 7))*AROW
                                        + ((lane >> 3) & 1)*8) * 2);
    const int irow = tid >> 2, iseg = tid & 3;      // irow 0..63

    auto issue = [&](int t) {
        const uint32_t base = sb + (t % 3)*STAGE_BYTES;
        #pragma unroll
        for (int i = 0; i < 2; i++) {
            const int row = irow + i*64;
            const uint32_t off = (uint32_t)((row*AROW + iseg*8)*2);
            const size_t gsrcA = (size_t)(n0+row)*lda + t*BK + iseg*8;
            const size_t gsrcB = (size_t)(c0+row)*ldb + t*BK + iseg*8;
            CP_ASYNC(base + AH_OFF + off, AHp + gsrcA);
            CP_ASYNC(base + AL_OFF + off, ALp + gsrcA);
            CP_ASYNC(base + BH_OFF + off, BHp + gsrcB);
            CP_ASYNC(base + BL_OFF + off, BLp + gsrcB);
        }
        CP_COMMIT();
    };

    issue(0); issue(1);
    #pragma unroll 1
    for (int t = 0; t < KCHUNKS; t++) {
        if (t + 2 < KCHUNKS) asm volatile("cp.async.wait_group 1;");
        else                 asm volatile("cp.async.wait_group 0;");
        __syncthreads();
        const uint32_t base = sb + (t % 3)*STAGE_BYTES;
        #pragma unroll
        for (int ks = 0; ks < 2; ks++) {
            uint32_t Ahf[2][4], Alf[2][4];
            LDSM_X4(Ahf[0], base + AH_OFF + a_off0 + ks*32);
            LDSM_X4(Ahf[1], base + AH_OFF + a_off1 + ks*32);
            LDSM_X4(Alf[0], base + AL_OFF + a_off0 + ks*32);
            LDSM_X4(Alf[1], base + AL_OFF + a_off1 + ks*32);
            #pragma unroll
            for (int bp = 0; bp < 4; bp++) {
                uint32_t Bhf[4], Blf[4];
                LDSM_X4(Bhf, base + BH_OFF + b_off + bp*16*AROW*2 + ks*32);
                LDSM_X4(Blf, base + BL_OFF + b_off + bp*16*AROW*2 + ks*32);
                #pragma unroll
                for (int am = 0; am < 2; am++) {
                    mma16816(acc[am][2*bp],   Ahf[am], Bhf[0], Bhf[1]);
                    mma16816(acc[am][2*bp+1], Ahf[am], Bhf[2], Bhf[3]);
                    mma16816(acc[am][2*bp],   Ahf[am], Blf[0], Blf[1]);
                    mma16816(acc[am][2*bp+1], Ahf[am], Blf[2], Blf[3]);
                    mma16816(acc[am][2*bp],   Alf[am], Bhf[0], Bhf[1]);
                    mma16816(acc[am][2*bp+1], Alf[am], Bhf[2], Bhf[3]);
                }
            }
        }
        __syncthreads();
        if (t + 2 < KCHUNKS) issue(t + 2);
    }
}

// ---------------- big GEMM + fused SLSTM epilogue ----------------
__global__ void __launch_bounds__(256) k_hgemm_big(
    const float* __restrict__ bias, const int* __restrict__ mask,
    float* __restrict__ out, int cur, int last)
{
    extern __shared__ char smem[];
    const int n0 = blockIdx.y*BM, c0 = blockIdx.x*BN;
    float acc[2][8][4] = {};
    hmma_mainloop<KXT/BK>(g_XH, g_XL, KXT, g_WH, g_WL, KXT, n0, c0, smem, acc);

    // stage z to smem (row stride 132 floats)
    float* zs = (float*)smem;
    const int lane = threadIdx.x & 31, wid = threadIdx.x >> 5;
    const int wm = wid >> 1, wn = wid & 1;
    const int g = lane >> 2, tg2 = (lane & 3)*2;
    __syncthreads();
    #pragma unroll
    for (int am = 0; am < 2; am++) {
        const int ra = wm*32 + am*16 + g;
        #pragma unroll
        for (int na = 0; na < 8; na++) {
            const int col = wn*64 + na*8 + tg2;
            *(float2*)&zs[ra*132 + col]     = *(float2*)&acc[am][na][0];
            *(float2*)&zs[(ra+8)*132 + col] = *(float2*)&acc[am][na][2];
        }
    }
    __syncthreads();

    // per-unit epilogue: 16 units x 128 rows in this tile
    const int u = threadIdx.x & 15, rgrp = threadIdx.x >> 4;   // 16 rgrps x 8 rows
    const int kout = (c0 >> 3) + u;
    const float* dc_old = g_dc[cur];
    float* hout = last ? out : g_h;
    float bz[8];
    #pragma unroll
    for (int gg = 0; gg < 8; gg++) bz[gg] = bias[gg*512 + kout];

    #pragma unroll 1
    for (int i = 0; i < 8; i++) {
        const int n = n0 + rgrp*8 + i;
        const int b = n >> 9;
        const float m = (float)mask[n];
        float z[8];
        *(float4*)&z[0] = *(float4*)&zs[(rgrp*8+i)*132 + u*8];
        *(float4*)&z[4] = *(float4*)&zs[(rgrp*8+i)*132 + u*8 + 4];
        #pragma unroll
        for (int gg = 0; gg < 8; gg++)
            z[gg] += g_zd[(b<<12)+(kout<<3)+gg] + bz[gg];
        float e[6], ssum = 0.f;
        #pragma unroll
        for (int j = 0; j < 6; j++) { e[j] = __expf(sigm(z[j])); ssum += e[j]; }
        const float inv = 1.f/ssum;
        const float o = sigm(z[6]);
        const float u_t = tanhf(z[7]);
        const size_t idx = ((size_t)n << 9) + kout;
        float cn = (e[0]*g_cb[idx] + e[1]*g_ca[idx] + e[2]*g_c[idx]
                  + e[3]*dc_old[(b<<9)+kout] + e[4]*g_swc[idx] + e[5]*u_t) * inv;
        cn *= m;
        const float hv = o * tanhf(cn) * m;
        hout[idx] = hv;
        g_c[idx]  = cn;
        split2h(hv, g_hH[idx], g_hL[idx]);
    }
}

// ---------------- gf GEMM: gf = sigmoid(h @ gWhf + gfx + gbf) + mask_score ----------------
__global__ void __launch_bounds__(256) k_hgemm_gf(
    const float* __restrict__ gbf, const int* __restrict__ mask)
{
    extern __shared__ char smem[];
    const int n0 = blockIdx.y*BM, c0 = blockIdx.x*BN;
    float acc[2][8][4] = {};
    hmma_mainloop<Hh/BK>(g_hH, g_hL, Hh, g_GH, g_GL, Hh, n0, c0, smem, acc);

    const int lane = threadIdx.x & 31, wid = threadIdx.x >> 5;
    const int wm = wid >> 1, wn = wid & 1;
    const int g = lane >> 2, tg2 = (lane & 3)*2;
    #pragma unroll
    for (int am = 0; am < 2; am++) {
        #pragma unroll
        for (int half = 0; half < 2; half++) {
            const int n = n0 + wm*32 + am*16 + g + half*8;
            const int b = n >> 9;
            const float ms = mask[n] ? 0.f : -1e25f;
            #pragma unroll
            for (int na = 0; na < 8; na++) {
                const int cc = c0 + wn*64 + na*8 + tg2;
                float2 r;
                r.x = sigm(acc[am][na][half*2+0] + g_gfx[(b<<9)+cc]   + gbf[cc])   + ms;
                r.y = sigm(acc[am][na][half*2+1] + g_gfx[(b<<9)+cc+1] + gbf[cc+1]) + ms;
                *(float2*)&g_gf[((size_t)n<<9) + cc] = r;
            }
        }
    }
}

// ---------------- weight rearrangement (one-time) ----------------
__global__ void k_prepw(const float* __restrict__ Wx, const float* __restrict__ Wh,
                        const float* __restrict__ Wi, const float* __restrict__ Ws) {
    size_t idx = (size_t)blockIdx.x*256 + threadIdx.x;   // < 4096*2560
    int c = (int)(idx / KXT), j = (int)(idx % KXT);
    int g = c & 7, k = c >> 3;
    float v;
    if (j < 512)        v = Wx[((size_t)((g<<9)  + j       ))*512 + k];
    else if (j < 1536)  v = Wh[((size_t)((g<<10) + (j-512) ))*512 + k];
    else if (j < 2048)  v = Ws[((size_t)((g<<9)  + (j-1536)))*512 + k];
    else                v = Wi[((size_t)((g<<9)  + (j-2048)))*512 + k];
    split2h(v, g_WH[idx], g_WL[idx]);
}

__global__ void k_prepgwf(const float* __restrict__ gWhf) {
    int idx = blockIdx.x*256 + threadIdx.x;   // < 512*512
    int kcol = idx >> 9, j = idx & 511;
    split2h(gWhf[j*512 + kcol], g_GH[idx], g_GL[idx]);
}

// ---------------- init ----------------
__global__ void k_init(const float* __restrict__ word, const float* __restrict__ ih,
                       const float* __restrict__ icc, const int* __restrict__ mask) {
    int n = blockIdx.x, k = threadIdx.x;
    float m = (float)mask[n];
    size_t i = ((size_t)n << 9) + k;
    float hv = ih[i]*m;
    g_h[i]  = hv;
    split2h(hv, g_hH[i], g_hL[i]);
    g_c[i]  = icc[i]*m;
    split2h(word[i]*m, g_XH[(size_t)n*KXT + 2048 + k], g_XL[(size_t)n*KXT + 2048 + k]);
}

// mode 0: mean(h)->comb   1: mean(h)->dh[0]   2: mean(c)->dc[0]
__global__ void k_mean(int mode) {
    int b = blockIdx.x, k = threadIdx.x;
    const float* x = (mode == 2) ? g_c : g_h;
    float s = 0.f;
    for (int t = 0; t < Ss; t++) s += x[(((size_t)(b<<9)) + t)*512 + k];
    s *= (1.f/512.f);
    int o = (b<<9) + k;
    if (mode == 0)      g_comb[o]  = s;
    else if (mode == 1) g_dh[0][o] = s;
    else                g_dc[0][o] = s;
}

// small per-batch GEMMs: gd, go, gfx, zd[g]
__global__ void k_small(const float* __restrict__ gW, const float* __restrict__ gb,
                        const float* __restrict__ Wd, int cur) {
    int t = blockIdx.y;
    int idx = blockIdx.x*256 + threadIdx.x;   // 0..16383 = (b,k)
    int b = idx >> 9, k = idx & 511;
    const float* dh = g_dh[cur] + (b<<9);
    float s = 0.f;
    if (t <= 1) {
        const float* W1 = gW + (size_t)(t*2  )*262144;
        const float* W2 = gW + (size_t)(t*2+1)*262144;
        const float* cm = g_comb + (b<<9);
        for (int j = 0; j < 512; j++)
            s = fmaf(dh[j], W1[j*512+k], fmaf(cm[j], W2[j*512+k], s));
        float v = sigm(s + gb[t*512 + k]);
        if (t == 0) g_gd[idx] = v; else g_go[idx] = v;
    } else if (t == 2) {
        const float* W = gW + (size_t)4*262144;   // gWxf
        for (int j = 0; j < 512; j++) s = fmaf(dh[j], W[j*512+k], s);
        g_gfx[idx] = s;
    } else {
        int g = t - 3;
        const float* W = Wd + (size_t)g*262144;
        for (int j = 0; j < 512; j++) s = fmaf(dh[j], W[j*512+k], s);
        g_zd[(b<<12) + (k<<3) + g] = s;
    }
}

// softmax over S+1 entries per (b,k) + new dummies
__global__ void k_soft(int cur) {
    int b = blockIdx.x, k = threadIdx.x;
    int bk = (b<<9) + k;
    float den = __expf(g_gd[bk] - 1.f);
    float num = den * g_dc[cur][bk];
    const float* gf = g_gf + (size_t)b*Ss*Hh + k;
    const float* cp = g_c  + (size_t)b*Ss*Hh + k;
    for (int s = 0; s < Ss; s++) {
        float w = __expf(gf[s*512] - 1.f);
        num = fmaf(w, cp[s*512], num);
        den += w;
    }
    float dcn = num/den;
    g_dc[cur^1][bk] = dcn;
    g_dh[cur^1][bk] = g_go[bk]*tanhf(dcn);
}

// X cols 0..2047 = [h | hb | ha | sw_h] split planes; also cb, ca, swc (fp32)
__global__ void k_build(const int* __restrict__ pos) {
    int n = blockIdx.x, k = threadIdx.x;
    int b = n >> 9, s = n & 511;
    size_t base = ((size_t)n << 9) + k;
    float hv = g_h[base];
    float hb = (s >= 1 ? g_h[base-512] : 0.f) + (s >= 2 ? g_h[base-1024] : 0.f);
    float ha = (s <= 510 ? g_h[base+512] : 0.f) + (s <= 509 ? g_h[base+1024] : 0.f);
    int p = pos[n];
    float sh = 0.f, sc = 0.f;
    if (p > 0) {
        size_t pb = ((size_t)((b<<9) + p - 1) << 9) + k;
        sh = g_h[pb]; sc = g_c[pb];
    }
    size_t xb = (size_t)n*KXT + k;
    split2h(hv, g_XH[xb],        g_XL[xb]);
    split2h(hb, g_XH[xb + 512],  g_XL[xb + 512]);
    split2h(ha, g_XH[xb + 1024], g_XL[xb + 1024]);
    split2h(sh, g_XH[xb + 1536], g_XL[xb + 1536]);
    g_cb[base]  = (s >= 1 ? g_c[base-512] : 0.f) + (s >= 2 ? g_c[base-1024] : 0.f);
    g_ca[base]  = (s <= 510 ? g_c[base+512] : 0.f) + (s <= 509 ? g_c[base+1024] : 0.f);
    g_swc[base] = sc;
}

// ---------------- host ----------------
extern "C" void kernel_launch(void* const* d_in, const int* in_sizes, int n_in,
                              void* d_out, int out_size) {
    const float* word = (const float*)d_in[0];
    const float* ih   = (const float*)d_in[1];
    const float* icc  = (const float*)d_in[2];
    const float* Wx   = (const float*)d_in[3];
    const float* Wh   = (const float*)d_in[4];
    const float* Wi   = (const float*)d_in[5];
    const float* Wd   = (const float*)d_in[6];
    const float* Ws   = (const float*)d_in[7];
    const float* bias = (const float*)d_in[8];
    const float* gW   = (const float*)d_in[9];
    const float* gb   = (const float*)d_in[10];
    const int*   pos  = (const int*)d_in[11];
    const int*   mask = (const int*)d_in[12];
    float* out = (float*)d_out;

    cudaFuncSetAttribute(k_hgemm_big, cudaFuncAttributeMaxDynamicSharedMemorySize, SMEM_BYTES);
    cudaFuncSetAttribute(k_hgemm_gf,  cudaFuncAttributeMaxDynamicSharedMemorySize, SMEM_BYTES);

    k_prepw  <<<(int)(((size_t)CN*KXT)/256), 256>>>(Wx, Wh, Wi, Ws);
    k_prepgwf<<<(Hh*Hh)/256, 256>>>(gW + (size_t)5*262144);
    k_init   <<<Nn, 512>>>(word, ih, icc, mask);
    k_mean   <<<Bb, 512>>>(1);
    k_mean   <<<Bb, 512>>>(2);

    dim3 gbig(CN/BN, Nn/BM);   // (32, 128)
    dim3 ggf (Hh/BN, Nn/BM);   // (4, 128)
    int cur = 0;
    for (int layer = 0; layer < NLAYERS; layer++) {
        k_mean <<<Bb, 512>>>(0);
        k_small<<<dim3(64, 11), 256>>>(gW, gb, Wd, cur);
        k_hgemm_gf<<<ggf, 256, SMEM_BYTES>>>(gb + 1024, mask);
        k_soft <<<Bb, 512>>>(cur);
        k_build<<<Nn, 512>>>(pos);
        k_hgemm_big<<<gbig, 256, SMEM_BYTES>>>(bias, mask, out, cur, layer == NLAYERS-1);
        cur ^= 1;
    }
}

// round 11
// speedup vs baseline: 1.8969x; 1.1363x over previous
#include <cuda_runtime.h>
#include <cuda_fp16.h>
#include <math.h>
#include <cstdint>

// Problem constants (fixed by reference setup_inputs)
#define Bb   32
#define Ss   512
#define Hh   512
#define Nn   (Bb*Ss)        // 16384 tokens
#define CN   4096           // 8 gates * H, interleaved c = k*8 + g
#define KXT  2560           // [h | hb | ha | sw_h | emb]
#define NLAYERS 4

// HMMA GEMM tiling: 128x128 tile, 256 threads, BK=64, split-fp16 3-term
#define BM 128
#define BN 128
#define BK 64
#define AROW 72                        // BK + 8 pad (halves); 144 bytes/row
#define PL_BYTES (128*AROW*2)          // 18432 per plane
#define AH_OFF 0
#define AL_OFF PL_BYTES
#define BH_OFF (2*PL_BYTES)
#define BL_OFF (3*PL_BYTES)
#define STAGE_BYTES (4*PL_BYTES)       // 73728
#define SMEM_BYTES (3*STAGE_BYTES)     // 221184 <= 227KB cap; zs 67584 fits

// ---------------- device scratch ----------------
__device__ __half g_XH [(size_t)Nn*KXT];   // A hi plane
__device__ __half g_XL [(size_t)Nn*KXT];   // A lo plane
__device__ __half g_WH [(size_t)CN*KXT];   // B hi plane [c][j]
__device__ __half g_WL [(size_t)CN*KXT];   // B lo plane
__device__ __half g_GH [(size_t)Hh*Hh];    // gWhf hi [c][j]
__device__ __half g_GL [(size_t)Hh*Hh];    // gWhf lo
__device__ __half g_hH [(size_t)Nn*Hh];    // h hi (gf GEMM A)
__device__ __half g_hL [(size_t)Nn*Hh];    // h lo
__device__ float g_h  [(size_t)Nn*Hh];
__device__ float g_c  [(size_t)Nn*Hh];
__device__ float g_cb [(size_t)Nn*Hh];
__device__ float g_ca [(size_t)Nn*Hh];
__device__ float g_swc[(size_t)Nn*Hh];
__device__ float g_gf [(size_t)Nn*Hh];
__device__ float g_zd [Bb*CN];
__device__ float g_dh [2][Bb*Hh];
__device__ float g_dc [2][Bb*Hh];
__device__ float g_comb[Bb*Hh];
__device__ float g_gd [Bb*Hh];
__device__ float g_go [Bb*Hh];
__device__ float g_gfx[Bb*Hh];

__device__ __forceinline__ float sigm(float x) { return 1.f/(1.f+__expf(-x)); }
__device__ __forceinline__ void split2h(float v, __half& hi, __half& lo) {
    hi = __float2half_rn(v);
    lo = __float2half_rn(v - __half2float(hi));
}

__device__ __forceinline__ uint32_t smem_u32(const void* p) {
    uint32_t a;
    asm("{ .reg .u64 t; cvta.to.shared.u64 t, %1; cvt.u32.u64 %0, t; }" : "=r"(a) : "l"(p));
    return a;
}
__device__ __forceinline__ void mma16816(float* c, const uint32_t* a, uint32_t b0, uint32_t b1) {
    asm volatile("mma.sync.aligned.m16n8k16.row.col.f32.f16.f16.f32 "
        "{%0,%1,%2,%3},{%4,%5,%6,%7},{%8,%9},{%0,%1,%2,%3};"
        : "+f"(c[0]), "+f"(c[1]), "+f"(c[2]), "+f"(c[3])
        : "r"(a[0]), "r"(a[1]), "r"(a[2]), "r"(a[3]), "r"(b0), "r"(b1));
}
#define LDSM_X4(r, addr) \
    asm volatile("ldmatrix.sync.aligned.m8n8.x4.shared.b16 {%0,%1,%2,%3},[%4];" \
        : "=r"((r)[0]), "=r"((r)[1]), "=r"((r)[2]), "=r"((r)[3]) : "r"(addr))
#define CP_ASYNC(dst, src) \
    asm volatile("cp.async.cg.shared.global [%0],[%1],16;" :: "r"(dst), "l"(src))
#define CP_COMMIT() asm volatile("cp.async.commit_group;")

// ---------------- split-fp16 HMMA mainloop: C[128x128], 3-term, BK=64 ----------------
template<int KCHUNKS>
__device__ __forceinline__ void hmma_mainloop(
    const __half* __restrict__ AHp, const __half* __restrict__ ALp, int lda,
    const __half* __restrict__ BHp, const __half* __restrict__ BLp, int ldb,
    int n0, int c0, char* smem, float acc[2][8][4])
{
    const int tid = threadIdx.x, lane = tid & 31, wid = tid >> 5;
    const int wm = wid >> 1, wn = wid & 1;          // 4x2 warps, warp tile 32x64
    const uint32_t sb = smem_u32(smem);

    const uint32_t a_off0 = (uint32_t)(((wm*32 + (lane & 15))*AROW + (lane >> 4)*8) * 2);
    const uint32_t a_off1 = a_off0 + 16*AROW*2;
    const uint32_t b_off  = (uint32_t)(((wn*64 + ((lane >> 4) << 3) + (lane & 7))*AROW
                                        + ((lane >> 3) & 1)*8) * 2);

    auto issue = [&](int t) {
        const uint32_t base = sb + (t % 3)*STAGE_BYTES;
        #pragma unroll
        for (int i = 0; i < 4; i++) {
            const int q = tid + i*256;              // 1024 segs per plane
            const int row = q >> 3, seg = q & 7;
            const uint32_t off = (uint32_t)((row*AROW + seg*8)*2);
            const size_t gsrcA = (size_t)(n0+row)*lda + t*BK + seg*8;
            const size_t gsrcB = (size_t)(c0+row)*ldb + t*BK + seg*8;
            CP_ASYNC(base + AH_OFF + off, AHp + gsrcA);
            CP_ASYNC(base + AL_OFF + off, ALp + gsrcA);
            CP_ASYNC(base + BH_OFF + off, BHp + gsrcB);
            CP_ASYNC(base + BL_OFF + off, BLp + gsrcB);
        }
        CP_COMMIT();
    };

    issue(0); issue(1);
    #pragma unroll 1
    for (int t = 0; t < KCHUNKS; t++) {
        if (t + 2 < KCHUNKS) asm volatile("cp.async.wait_group 1;");
        else                 asm volatile("cp.async.wait_group 0;");
        __syncthreads();
        if (t + 2 < KCHUNKS) issue(t + 2);          // stage (t-1)%3: safe post-barrier
        const uint32_t base = sb + (t % 3)*STAGE_BYTES;
        #pragma unroll
        for (int ks = 0; ks < 4; ks++) {
            const uint32_t kb = (uint32_t)(ks*32);  // 16 halves per k-step
            uint32_t Ahf[2][4], Alf[2][4];
            LDSM_X4(Ahf[0], base + AH_OFF + a_off0 + kb);
            LDSM_X4(Ahf[1], base + AH_OFF + a_off1 + kb);
            LDSM_X4(Alf[0], base + AL_OFF + a_off0 + kb);
            LDSM_X4(Alf[1], base + AL_OFF + a_off1 + kb);
            #pragma unroll
            for (int bp = 0; bp < 4; bp++) {
                uint32_t Bhf[4], Blf[4];
                LDSM_X4(Bhf, base + BH_OFF + b_off + bp*16*AROW*2 + kb);
                LDSM_X4(Blf, base + BL_OFF + b_off + bp*16*AROW*2 + kb);
                #pragma unroll
                for (int am = 0; am < 2; am++) {
                    mma16816(acc[am][2*bp],   Ahf[am], Bhf[0], Bhf[1]);
                    mma16816(acc[am][2*bp+1], Ahf[am], Bhf[2], Bhf[3]);
                    mma16816(acc[am][2*bp],   Ahf[am], Blf[0], Blf[1]);
                    mma16816(acc[am][2*bp+1], Ahf[am], Blf[2], Blf[3]);
                    mma16816(acc[am][2*bp],   Alf[am], Bhf[0], Bhf[1]);
                    mma16816(acc[am][2*bp+1], Alf[am], Bhf[2], Bhf[3]);
                }
            }
        }
    }
}

// ---------------- big GEMM + fused SLSTM epilogue ----------------
__global__ void __launch_bounds__(256) k_hgemm_big(
    const float* __restrict__ bias, const int* __restrict__ mask,
    float* __restrict__ out, int cur, int last)
{
    extern __shared__ char smem[];
    const int n0 = blockIdx.y*BM, c0 = blockIdx.x*BN;
    float acc[2][8][4] = {};
    hmma_mainloop<KXT/BK>(g_XH, g_XL, KXT, g_WH, g_WL, KXT, n0, c0, smem, acc);

    // stage z to smem (row stride 132 floats)
    float* zs = (float*)smem;
    const int lane = threadIdx.x & 31, wid = threadIdx.x >> 5;
    const int wm = wid >> 1, wn = wid & 1;
    const int g = lane >> 2, tg2 = (lane & 3)*2;
    __syncthreads();
    #pragma unroll
    for (int am = 0; am < 2; am++) {
        const int ra = wm*32 + am*16 + g;
        #pragma unroll
        for (int na = 0; na < 8; na++) {
            const int col = wn*64 + na*8 + tg2;
            *(float2*)&zs[ra*132 + col]     = *(float2*)&acc[am][na][0];
            *(float2*)&zs[(ra+8)*132 + col] = *(float2*)&acc[am][na][2];
        }
    }
    __syncthreads();

    // per-unit epilogue: 16 units x 128 rows in this tile
    const int u = threadIdx.x & 15, rgrp = threadIdx.x >> 4;   // 16 rgrps x 8 rows
    const int kout = (c0 >> 3) + u;
    const float* dc_old = g_dc[cur];
    float* hout = last ? out : g_h;
    float bz[8];
    #pragma unroll
    for (int gg = 0; gg < 8; gg++) bz[gg] = bias[gg*512 + kout];

    #pragma unroll 1
    for (int i = 0; i < 8; i++) {
        const int n = n0 + rgrp*8 + i;
        const int b = n >> 9;
        const float m = (float)mask[n];
        float z[8];
        *(float4*)&z[0] = *(float4*)&zs[(rgrp*8+i)*132 + u*8];
        *(float4*)&z[4] = *(float4*)&zs[(rgrp*8+i)*132 + u*8 + 4];
        #pragma unroll
        for (int gg = 0; gg < 8; gg++)
            z[gg] += g_zd[(b<<12)+(kout<<3)+gg] + bz[gg];
        float e[6], ssum = 0.f;
        #pragma unroll
        for (int j = 0; j < 6; j++) { e[j] = __expf(sigm(z[j])); ssum += e[j]; }
        const float inv = 1.f/ssum;
        const float o = sigm(z[6]);
        const float u_t = tanhf(z[7]);
        const size_t idx = ((size_t)n << 9) + kout;
        float cn = (e[0]*g_cb[idx] + e[1]*g_ca[idx] + e[2]*g_c[idx]
                  + e[3]*dc_old[(b<<9)+kout] + e[4]*g_swc[idx] + e[5]*u_t) * inv;
        cn *= m;
        const float hv = o * tanhf(cn) * m;
        hout[idx] = hv;
        g_c[idx]  = cn;
        split2h(hv, g_hH[idx], g_hL[idx]);
    }
}

// ---------------- gf GEMM: gf = sigmoid(h @ gWhf + gfx + gbf) + mask_score ----------------
__global__ void __launch_bounds__(256) k_hgemm_gf(
    const float* __restrict__ gbf, const int* __restrict__ mask)
{
    extern __shared__ char smem[];
    const int n0 = blockIdx.y*BM, c0 = blockIdx.x*BN;
    float acc[2][8][4] = {};
    hmma_mainloop<Hh/BK>(g_hH, g_hL, Hh, g_GH, g_GL, Hh, n0, c0, smem, acc);

    const int lane = threadIdx.x & 31, wid = threadIdx.x >> 5;
    const int wm = wid >> 1, wn = wid & 1;
    const int g = lane >> 2, tg2 = (lane & 3)*2;
    #pragma unroll
    for (int am = 0; am < 2; am++) {
        #pragma unroll
        for (int half = 0; half < 2; half++) {
            const int n = n0 + wm*32 + am*16 + g + half*8;
            const int b = n >> 9;
            const float ms = mask[n] ? 0.f : -1e25f;
            #pragma unroll
            for (int na = 0; na < 8; na++) {
                const int cc = c0 + wn*64 + na*8 + tg2;
                float2 r;
                r.x = sigm(acc[am][na][half*2+0] + g_gfx[(b<<9)+cc]   + gbf[cc])   + ms;
                r.y = sigm(acc[am][na][half*2+1] + g_gfx[(b<<9)+cc+1] + gbf[cc+1]) + ms;
                *(float2*)&g_gf[((size_t)n<<9) + cc] = r;
            }
        }
    }
}

// ---------------- weight rearrangement (one-time; merged W + gWhf) ----------------
__global__ void k_prep(const float* __restrict__ Wx, const float* __restrict__ Wh,
                       const float* __restrict__ Wi, const float* __restrict__ Ws,
                       const float* __restrict__ gWhf) {
    size_t idx = (size_t)blockIdx.x*256 + threadIdx.x;
    if (idx < (size_t)CN*KXT) {
        int c = (int)(idx / KXT), j = (int)(idx % KXT);
        int g = c & 7, k = c >> 3;
        float v;
        if (j < 512)        v = Wx[((size_t)((g<<9)  + j       ))*512 + k];
        else if (j < 1536)  v = Wh[((size_t)((g<<10) + (j-512) ))*512 + k];
        else if (j < 2048)  v = Ws[((size_t)((g<<9)  + (j-1536)))*512 + k];
        else                v = Wi[((size_t)((g<<9)  + (j-2048)))*512 + k];
        split2h(v, g_WH[idx], g_WL[idx]);
    } else {
        int r = (int)(idx - (size_t)CN*KXT);        // < 512*512
        int kcol = r >> 9, j = r & 511;
        split2h(gWhf[j*512 + kcol], g_GH[r], g_GL[r]);
    }
}

// ---------------- init ----------------
__global__ void k_init(const float* __restrict__ word, const float* __restrict__ ih,
                       const float* __restrict__ icc, const int* __restrict__ mask) {
    int n = blockIdx.x, k = threadIdx.x;
    float m = (float)mask[n];
    size_t i = ((size_t)n << 9) + k;
    float hv = ih[i]*m;
    g_h[i]  = hv;
    split2h(hv, g_hH[i], g_hL[i]);
    g_c[i]  = icc[i]*m;
    split2h(word[i]*m, g_XH[(size_t)n*KXT + 2048 + k], g_XL[(size_t)n*KXT + 2048 + k]);
}

// mean(h)->dh[0] (y=0) and mean(c)->dc[0] (y=1), 4-way unrolled for MLP
__global__ void k_meanhc() {
    int b = blockIdx.x, k = threadIdx.x;
    const float* x = (blockIdx.y ? g_c : g_h) + ((size_t)(b<<9))*512 + k;
    float s0=0.f, s1=0.f, s2=0.f, s3=0.f;
    for (int t = 0; t < Ss; t += 4) {
        s0 += x[(size_t)t*512];       s1 += x[(size_t)(t+1)*512];
        s2 += x[(size_t)(t+2)*512];   s3 += x[(size_t)(t+3)*512];
    }
    float s = ((s0+s1)+(s2+s3)) * (1.f/512.f);
    int o = (b<<9) + k;
    if (blockIdx.y) g_dc[0][o] = s; else g_dh[0][o] = s;
}

// mean(h)->comb (per layer)
__global__ void k_mean0() {
    int b = blockIdx.x, k = threadIdx.x;
    const float* x = g_h + ((size_t)(b<<9))*512 + k;
    float s0=0.f, s1=0.f, s2=0.f, s3=0.f;
    for (int t = 0; t < Ss; t += 4) {
        s0 += x[(size_t)t*512];       s1 += x[(size_t)(t+1)*512];
        s2 += x[(size_t)(t+2)*512];   s3 += x[(size_t)(t+3)*512];
    }
    g_comb[(b<<9) + k] = ((s0+s1)+(s2+s3)) * (1.f/512.f);
}

// small per-batch GEMMs: gd, go, gfx, zd[g]
__global__ void k_small(const float* __restrict__ gW, const float* __restrict__ gb,
                        const float* __restrict__ Wd, int cur) {
    int t = blockIdx.y;
    int idx = blockIdx.x*256 + threadIdx.x;   // 0..16383 = (b,k)
    int b = idx >> 9, k = idx & 511;
    const float* dh = g_dh[cur] + (b<<9);
    float s = 0.f;
    if (t <= 1) {
        const float* W1 = gW + (size_t)(t*2  )*262144;
        const float* W2 = gW + (size_t)(t*2+1)*262144;
        const float* cm = g_comb + (b<<9);
        for (int j = 0; j < 512; j++)
            s = fmaf(dh[j], W1[j*512+k], fmaf(cm[j], W2[j*512+k], s));
        float v = sigm(s + gb[t*512 + k]);
        if (t == 0) g_gd[idx] = v; else g_go[idx] = v;
    } else if (t == 2) {
        const float* W = gW + (size_t)4*262144;   // gWxf
        for (int j = 0; j < 512; j++) s = fmaf(dh[j], W[j*512+k], s);
        g_gfx[idx] = s;
    } else {
        int g = t - 3;
        const float* W = Wd + (size_t)g*262144;
        for (int j = 0; j < 512; j++) s = fmaf(dh[j], W[j*512+k], s);
        g_zd[(b<<12) + (k<<3) + g] = s;
    }
}

// softmax over S+1 entries per (b,k) + new dummies
__global__ void k_soft(int cur) {
    int b = blockIdx.x, k = threadIdx.x;
    int bk = (b<<9) + k;
    float den = __expf(g_gd[bk] - 1.f);
    float num = den * g_dc[cur][bk];
    const float* gf = g_gf + (size_t)b*Ss*Hh + k;
    const float* cp = g_c  + (size_t)b*Ss*Hh + k;
    for (int s = 0; s < Ss; s++) {
        float w = __expf(gf[s*512] - 1.f);
        num = fmaf(w, cp[s*512], num);
        den += w;
    }
    float dcn = num/den;
    g_dc[cur^1][bk] = dcn;
    g_dh[cur^1][bk] = g_go[bk]*tanhf(dcn);
}

// X cols 0..2047 = [h | hb | ha | sw_h] split planes; also cb, ca, swc (fp32)
__global__ void k_build(const int* __restrict__ pos) {
    int n = blockIdx.x, k = threadIdx.x;
    int b = n >> 9, s = n & 511;
    size_t base = ((size_t)n << 9) + k;
    float hv = g_h[base];
    float hb = (s >= 1 ? g_h[base-512] : 0.f) + (s >= 2 ? g_h[base-1024] : 0.f);
    float ha = (s <= 510 ? g_h[base+512] : 0.f) + (s <= 509 ? g_h[base+1024] : 0.f);
    int p = pos[n];
    float sh = 0.f, sc = 0.f;
    if (p > 0) {
        size_t pb = ((size_t)((b<<9) + p - 1) << 9) + k;
        sh = g_h[pb]; sc = g_c[pb];
    }
    size_t xb = (size_t)n*KXT + k;
    split2h(hv, g_XH[xb],        g_XL[xb]);
    split2h(hb, g_XH[xb + 512],  g_XL[xb + 512]);
    split2h(ha, g_XH[xb + 1024], g_XL[xb + 1024]);
    split2h(sh, g_XH[xb + 1536], g_XL[xb + 1536]);
    g_cb[base]  = (s >= 1 ? g_c[base-512] : 0.f) + (s >= 2 ? g_c[base-1024] : 0.f);
    g_ca[base]  = (s <= 510 ? g_c[base+512] : 0.f) + (s <= 509 ? g_c[base+1024] : 0.f);
    g_swc[base] = sc;
}

// ---------------- host ----------------
extern "C" void kernel_launch(void* const* d_in, const int* in_sizes, int n_in,
                              void* d_out, int out_size) {
    const float* word = (const float*)d_in[0];
    const float* ih   = (const float*)d_in[1];
    const float* icc  = (const float*)d_in[2];
    const float* Wx   = (const float*)d_in[3];
    const float* Wh   = (const float*)d_in[4];
    const float* Wi   = (const float*)d_in[5];
    const float* Wd   = (const float*)d_in[6];
    const float* Ws   = (const float*)d_in[7];
    const float* bias = (const float*)d_in[8];
    const float* gW   = (const float*)d_in[9];
    const float* gb   = (const float*)d_in[10];
    const int*   pos  = (const int*)d_in[11];
    const int*   mask = (const int*)d_in[12];
    float* out = (float*)d_out;

    cudaFuncSetAttribute(k_hgemm_big, cudaFuncAttributeMaxDynamicSharedMemorySize, SMEM_BYTES);
    cudaFuncSetAttribute(k_hgemm_gf,  cudaFuncAttributeMaxDynamicSharedMemorySize, SMEM_BYTES);

    // launch order: prep(0), init(1), meanhc(2), then per layer
    // [mean0, small, gf, soft, build, big] -> first gf GEMM is launch index 5 (ncu -s 5)
    const int prep_blocks = (int)(((size_t)CN*KXT + (size_t)Hh*Hh)/256);
    k_prep  <<<prep_blocks, 256>>>(Wx, Wh, Wi, Ws, gW + (size_t)5*262144);
    k_init  <<<Nn, 512>>>(word, ih, icc, mask);
    k_meanhc<<<dim3(Bb, 2), 512>>>();

    dim3 gbig(CN/BN, Nn/BM);   // (32, 128)
    dim3 ggf (Hh/BN, Nn/BM);   // (4, 128)
    int cur = 0;
    for (int layer = 0; layer < NLAYERS; layer++) {
        k_mean0<<<Bb, 512>>>();
        k_small<<<dim3(64, 11), 256>>>(gW, gb, Wd, cur);
        k_hgemm_gf<<<ggf, 256, SMEM_BYTES>>>(gb + 1024, mask);
        k_soft <<<Bb, 512>>>(cur);
        k_build<<<Nn, 512>>>(pos);
        k_hgemm_big<<<gbig, 256, SMEM_BYTES>>>(bias, mask, out, cur, layer == NLAYERS-1);
        cur ^= 1;
    }
}

// round 12
// speedup vs baseline: 2.5695x; 1.3546x over previous
#include <cuda_runtime.h>
#include <cuda_fp16.h>
#include <math.h>
#include <cstdint>

// Problem constants (fixed by reference setup_inputs)
#define Bb   32
#define Ss   512
#define Hh   512
#define Nn   (Bb*Ss)        // 16384 tokens
#define CN   4096           // 8 gates * H, interleaved c = k*8 + g
#define KXT  2560           // [h | hb | ha | sw_h | emb]
#define NLAYERS 4

// HMMA GEMM: 128x128 tile, 256 threads, BK=64, 2-term (A fp16, B split hi/lo)
#define BM 128
#define BN 128
#define BK 64
#define AROW 72                        // BK + 8 pad (halves); 144 bytes/row
#define PL_BYTES (128*AROW*2)          // 18432 per plane
#define A_OFF  0
#define BH_OFF PL_BYTES
#define BL_OFF (2*PL_BYTES)
#define STAGE_BYTES (3*PL_BYTES)       // 55296
#define NSTG 4
#define SMEM_BYTES (NSTG*STAGE_BYTES)  // 221184 <= 227KB; zs 67584 fits

// ---------------- device scratch ----------------
__device__ __half g_XA [(size_t)Nn*KXT];   // A single fp16
__device__ __half g_WH [(size_t)CN*KXT];   // B hi plane [c][j]
__device__ __half g_WL [(size_t)CN*KXT];   // B lo plane
__device__ __half g_GH [(size_t)Hh*Hh];    // gWhf hi [c][j]
__device__ __half g_GL [(size_t)Hh*Hh];    // gWhf lo
__device__ __half g_hA [(size_t)Nn*Hh];    // h fp16 (gf GEMM A)
__device__ float g_h  [(size_t)Nn*Hh];
__device__ float g_c  [(size_t)Nn*Hh];
__device__ float g_cb [(size_t)Nn*Hh];
__device__ float g_ca [(size_t)Nn*Hh];
__device__ float g_swc[(size_t)Nn*Hh];
__device__ float g_gf [(size_t)Nn*Hh];
__device__ float g_zd [Bb*CN];
__device__ float g_dh [2][Bb*Hh];
__device__ float g_dc [2][Bb*Hh];
__device__ float g_comb[Bb*Hh];
__device__ float g_gd [Bb*Hh];
__device__ float g_go [Bb*Hh];
__device__ float g_gfx[Bb*Hh];

__device__ __forceinline__ float sigm(float x) { return 1.f/(1.f+__expf(-x)); }
__device__ __forceinline__ void split2h(float v, __half& hi, __half& lo) {
    hi = __float2half_rn(v);
    lo = __float2half_rn(v - __half2float(hi));
}

__device__ __forceinline__ uint32_t smem_u32(const void* p) {
    uint32_t a;
    asm("{ .reg .u64 t; cvta.to.shared.u64 t, %1; cvt.u32.u64 %0, t; }" : "=r"(a) : "l"(p));
    return a;
}
__device__ __forceinline__ void mma16816(float* c, const uint32_t* a, uint32_t b0, uint32_t b1) {
    asm volatile("mma.sync.aligned.m16n8k16.row.col.f32.f16.f16.f32 "
        "{%0,%1,%2,%3},{%4,%5,%6,%7},{%8,%9},{%0,%1,%2,%3};"
        : "+f"(c[0]), "+f"(c[1]), "+f"(c[2]), "+f"(c[3])
        : "r"(a[0]), "r"(a[1]), "r"(a[2]), "r"(a[3]), "r"(b0), "r"(b1));
}
#define LDSM_X4(r, addr) \
    asm volatile("ldmatrix.sync.aligned.m8n8.x4.shared.b16 {%0,%1,%2,%3},[%4];" \
        : "=r"((r)[0]), "=r"((r)[1]), "=r"((r)[2]), "=r"((r)[3]) : "r"(addr))
#define CP_ASYNC(dst, src) \
    asm volatile("cp.async.cg.shared.global [%0],[%1],16;" :: "r"(dst), "l"(src))
#define CP_COMMIT() asm volatile("cp.async.commit_group;")

// ---------------- 2-term HMMA mainloop: C[128x128], BK=64, 4 stages ----------------
template<int KCHUNKS>
__device__ __forceinline__ void hmma_mainloop(
    const __half* __restrict__ AAp, int lda,
    const __half* __restrict__ BHp, const __half* __restrict__ BLp, int ldb,
    int n0, int c0, char* smem, float acc[2][8][4])
{
    const int tid = threadIdx.x, lane = tid & 31, wid = tid >> 5;
    const int wm = wid >> 1, wn = wid & 1;          // 4x2 warps, warp tile 32x64
    const uint32_t sb = smem_u32(smem);

    const uint32_t a_off0 = (uint32_t)(((wm*32 + (lane & 15))*AROW + (lane >> 4)*8) * 2);
    const uint32_t a_off1 = a_off0 + 16*AROW*2;
    const uint32_t b_off  = (uint32_t)(((wn*64 + ((lane >> 4) << 3) + (lane & 7))*AROW
                                        + ((lane >> 3) & 1)*8) * 2);

    auto issue = [&](int t) {
        const uint32_t base = sb + (t % NSTG)*STAGE_BYTES;
        #pragma unroll
        for (int i = 0; i < 4; i++) {
            const int q = tid + i*256;              // 1024 segs per plane
            const int row = q >> 3, seg = q & 7;
            const uint32_t off = (uint32_t)((row*AROW + seg*8)*2);
            const size_t gsrcA = (size_t)(n0+row)*lda + t*BK + seg*8;
            const size_t gsrcB = (size_t)(c0+row)*ldb + t*BK + seg*8;
            CP_ASYNC(base + A_OFF  + off, AAp + gsrcA);
            CP_ASYNC(base + BH_OFF + off, BHp + gsrcB);
            CP_ASYNC(base + BL_OFF + off, BLp + gsrcB);
        }
        CP_COMMIT();
    };

    issue(0); issue(1); issue(2);
    #pragma unroll 1
    for (int t = 0; t < KCHUNKS; t++) {
        if (t + 3 <= KCHUNKS)      asm volatile("cp.async.wait_group 2;");
        else if (t + 2 <= KCHUNKS) asm volatile("cp.async.wait_group 1;");
        else                       asm volatile("cp.async.wait_group 0;");
        __syncthreads();
        if (t + 3 < KCHUNKS) issue(t + 3);          // stage (t-1)%4: safe post-barrier
        const uint32_t base = sb + (t % NSTG)*STAGE_BYTES;
        #pragma unroll
        for (int ks = 0; ks < 4; ks++) {
            const uint32_t kb = (uint32_t)(ks*32);  // 16 halves per k-step
            uint32_t Ahf[2][4];
            LDSM_X4(Ahf[0], base + A_OFF + a_off0 + kb);
            LDSM_X4(Ahf[1], base + A_OFF + a_off1 + kb);
            #pragma unroll
            for (int bp = 0; bp < 4; bp++) {
                uint32_t Bhf[4], Blf[4];
                LDSM_X4(Bhf, base + BH_OFF + b_off + bp*16*AROW*2 + kb);
                LDSM_X4(Blf, base + BL_OFF + b_off + bp*16*AROW*2 + kb);
                #pragma unroll
                for (int am = 0; am < 2; am++) {
                    mma16816(acc[am][2*bp],   Ahf[am], Bhf[0], Bhf[1]);
                    mma16816(acc[am][2*bp+1], Ahf[am], Bhf[2], Bhf[3]);
                    mma16816(acc[am][2*bp],   Ahf[am], Blf[0], Blf[1]);
                    mma16816(acc[am][2*bp+1], Ahf[am], Blf[2], Blf[3]);
                }
            }
        }
    }
}

// ---------------- big GEMM + fused SLSTM epilogue ----------------
__global__ void __launch_bounds__(256) k_hgemm_big(
    const float* __restrict__ bias, const int* __restrict__ mask,
    float* __restrict__ out, int cur, int last)
{
    extern __shared__ char smem[];
    const int n0 = blockIdx.y*BM, c0 = blockIdx.x*BN;
    float acc[2][8][4] = {};
    hmma_mainloop<KXT/BK>(g_XA, KXT, g_WH, g_WL, KXT, n0, c0, smem, acc);

    // stage z to smem (row stride 132 floats)
    float* zs = (float*)smem;
    const int lane = threadIdx.x & 31, wid = threadIdx.x >> 5;
    const int wm = wid >> 1, wn = wid & 1;
    const int g = lane >> 2, tg2 = (lane & 3)*2;
    __syncthreads();
    #pragma unroll
    for (int am = 0; am < 2; am++) {
        const int ra = wm*32 + am*16 + g;
        #pragma unroll
        for (int na = 0; na < 8; na++) {
            const int col = wn*64 + na*8 + tg2;
            *(float2*)&zs[ra*132 + col]     = *(float2*)&acc[am][na][0];
            *(float2*)&zs[(ra+8)*132 + col] = *(float2*)&acc[am][na][2];
        }
    }
    __syncthreads();

    // per-unit epilogue: 16 units x 128 rows in this tile
    const int u = threadIdx.x & 15, rgrp = threadIdx.x >> 4;   // 16 rgrps x 8 rows
    const int kout = (c0 >> 3) + u;
    const float* dc_old = g_dc[cur];
    float* hout = last ? out : g_h;
    float bz[8];
    #pragma unroll
    for (int gg = 0; gg < 8; gg++) bz[gg] = bias[gg*512 + kout];

    #pragma unroll 1
    for (int i = 0; i < 8; i++) {
        const int n = n0 + rgrp*8 + i;
        const int b = n >> 9;
        const float m = (float)mask[n];
        float z[8];
        *(float4*)&z[0] = *(float4*)&zs[(rgrp*8+i)*132 + u*8];
        *(float4*)&z[4] = *(float4*)&zs[(rgrp*8+i)*132 + u*8 + 4];
        #pragma unroll
        for (int gg = 0; gg < 8; gg++)
            z[gg] += g_zd[(b<<12)+(kout<<3)+gg] + bz[gg];
        float e[6], ssum = 0.f;
        #pragma unroll
        for (int j = 0; j < 6; j++) { e[j] = __expf(sigm(z[j])); ssum += e[j]; }
        const float inv = 1.f/ssum;
        const float o = sigm(z[6]);
        const float u_t = tanhf(z[7]);
        const size_t idx = ((size_t)n << 9) + kout;
        float cn = (e[0]*g_cb[idx] + e[1]*g_ca[idx] + e[2]*g_c[idx]
                  + e[3]*dc_old[(b<<9)+kout] + e[4]*g_swc[idx] + e[5]*u_t) * inv;
        cn *= m;
        const float hv = o * tanhf(cn) * m;
        hout[idx] = hv;
        g_c[idx]  = cn;
        g_hA[idx] = __float2half_rn(hv);
    }
}

// ---------------- gf GEMM: gf = sigmoid(h @ gWhf + gfx + gbf) + mask_score ----------------
__global__ void __launch_bounds__(256) k_hgemm_gf(
    const float* __restrict__ gbf, const int* __restrict__ mask)
{
    extern __shared__ char smem[];
    const int n0 = blockIdx.y*BM, c0 = blockIdx.x*BN;
    float acc[2][8][4] = {};
    hmma_mainloop<Hh/BK>(g_hA, Hh, g_GH, g_GL, Hh, n0, c0, smem, acc);

    const int lane = threadIdx.x & 31, wid = threadIdx.x >> 5;
    const int wm = wid >> 1, wn = wid & 1;
    const int g = lane >> 2, tg2 = (lane & 3)*2;
    #pragma unroll
    for (int am = 0; am < 2; am++) {
        #pragma unroll
        for (int half = 0; half < 2; half++) {
            const int n = n0 + wm*32 + am*16 + g + half*8;
            const int b = n >> 9;
            const float ms = mask[n] ? 0.f : -1e25f;
            #pragma unroll
            for (int na = 0; na < 8; na++) {
                const int cc = c0 + wn*64 + na*8 + tg2;
                float2 r;
                r.x = sigm(acc[am][na][half*2+0] + g_gfx[(b<<9)+cc]   + gbf[cc])   + ms;
                r.y = sigm(acc[am][na][half*2+1] + g_gfx[(b<<9)+cc+1] + gbf[cc+1]) + ms;
                *(float2*)&g_gf[((size_t)n<<9) + cc] = r;
            }
        }
    }
}

// ---------------- one-time prep (weights) + init (inputs), merged ----------------
#define PREP_ELEMS ((size_t)CN*KXT + (size_t)Hh*Hh)
#define PREP_BLOCKS ((int)(PREP_ELEMS/256))          // 41984
#define INIT_BLOCKS ((Nn*Hh)/256)                    // 32768
__global__ void k_prep_init(
    const float* __restrict__ Wx, const float* __restrict__ Wh,
    const float* __restrict__ Wi, const float* __restrict__ Ws,
    const float* __restrict__ gWhf,
    const float* __restrict__ word, const float* __restrict__ ih,
    const float* __restrict__ icc, const int* __restrict__ mask)
{
    if (blockIdx.x < PREP_BLOCKS) {
        size_t idx = (size_t)blockIdx.x*256 + threadIdx.x;
        if (idx < (size_t)CN*KXT) {
            int c = (int)(idx / KXT), j = (int)(idx % KXT);
            int g = c & 7, k = c >> 3;
            float v;
            if (j < 512)        v = Wx[((size_t)((g<<9)  + j       ))*512 + k];
            else if (j < 1536)  v = Wh[((size_t)((g<<10) + (j-512) ))*512 + k];
            else if (j < 2048)  v = Ws[((size_t)((g<<9)  + (j-1536)))*512 + k];
            else                v = Wi[((size_t)((g<<9)  + (j-2048)))*512 + k];
            split2h(v, g_WH[idx], g_WL[idx]);
        } else {
            int r = (int)(idx - (size_t)CN*KXT);     // < 512*512
            int kcol = r >> 9, j = r & 511;
            split2h(gWhf[j*512 + kcol], g_GH[r], g_GL[r]);
        }
    } else {
        size_t idx = (size_t)(blockIdx.x - PREP_BLOCKS)*256 + threadIdx.x;  // < Nn*512
        int n = (int)(idx >> 9), k = (int)(idx & 511);
        float m = (float)mask[n];
        float hv = ih[idx]*m;
        g_h[idx]  = hv;
        g_hA[idx] = __float2half_rn(hv);
        g_c[idx]  = icc[idx]*m;
        g_XA[(size_t)n*KXT + 2048 + k] = __float2half_rn(word[idx]*m);
    }
}

// mean(h)->dh[0] (y=0) and mean(c)->dc[0] (y=1), 4-way unrolled for MLP
__global__ void k_meanhc() {
    int b = blockIdx.x, k = threadIdx.x;
    const float* x = (blockIdx.y ? g_c : g_h) + ((size_t)(b<<9))*512 + k;
    float s0=0.f, s1=0.f, s2=0.f, s3=0.f;
    for (int t = 0; t < Ss; t += 4) {
        s0 += x[(size_t)t*512];       s1 += x[(size_t)(t+1)*512];
        s2 += x[(size_t)(t+2)*512];   s3 += x[(size_t)(t+3)*512];
    }
    float s = ((s0+s1)+(s2+s3)) * (1.f/512.f);
    int o = (b<<9) + k;
    if (blockIdx.y) g_dc[0][o] = s; else g_dh[0][o] = s;
}

// mean(h)->comb (layers >= 1)
__global__ void k_mean0() {
    int b = blockIdx.x, k = threadIdx.x;
    const float* x = g_h + ((size_t)(b<<9))*512 + k;
    float s0=0.f, s1=0.f, s2=0.f, s3=0.f;
    for (int t = 0; t < Ss; t += 4) {
        s0 += x[(size_t)t*512];       s1 += x[(size_t)(t+1)*512];
        s2 += x[(size_t)(t+2)*512];   s3 += x[(size_t)(t+3)*512];
    }
    g_comb[(b<<9) + k] = ((s0+s1)+(s2+s3)) * (1.f/512.f);
}

// small per-batch GEMMs: gd, go, gfx, zd[g]. layer0: comb == dh[0]
__global__ void k_small(const float* __restrict__ gW, const float* __restrict__ gb,
                        const float* __restrict__ Wd, int cur, int layer0) {
    int t = blockIdx.y;
    int idx = blockIdx.x*256 + threadIdx.x;   // 0..16383 = (b,k)
    int b = idx >> 9, k = idx & 511;
    const float* dh = g_dh[cur] + (b<<9);
    float s = 0.f;
    if (t <= 1) {
        const float* W1 = gW + (size_t)(t*2  )*262144;
        const float* W2 = gW + (size_t)(t*2+1)*262144;
        const float* cm = (layer0 ? g_dh[cur] : g_comb) + (b<<9);
        for (int j = 0; j < 512; j++)
            s = fmaf(dh[j], W1[j*512+k], fmaf(cm[j], W2[j*512+k], s));
        float v = sigm(s + gb[t*512 + k]);
        if (t == 0) g_gd[idx] = v; else g_go[idx] = v;
    } else if (t == 2) {
        const float* W = gW + (size_t)4*262144;   // gWxf
        for (int j = 0; j < 512; j++) s = fmaf(dh[j], W[j*512+k], s);
        g_gfx[idx] = s;
    } else {
        int g = t - 3;
        const float* W = Wd + (size_t)g*262144;
        for (int j = 0; j < 512; j++) s = fmaf(dh[j], W[j*512+k], s);
        g_zd[(b<<12) + (k<<3) + g] = s;
    }
}

// softmax over S+1 entries per (b,k) + new dummies
__global__ void k_soft(int cur) {
    int b = blockIdx.x, k = threadIdx.x;
    int bk = (b<<9) + k;
    float den = __expf(g_gd[bk] - 1.f);
    float num = den * g_dc[cur][bk];
    const float* gf = g_gf + (size_t)b*Ss*Hh + k;
    const float* cp = g_c  + (size_t)b*Ss*Hh + k;
    for (int s = 0; s < Ss; s++) {
        float w = __expf(gf[s*512] - 1.f);
        num = fmaf(w, cp[s*512], num);
        den += w;
    }
    float dcn = num/den;
    g_dc[cur^1][bk] = dcn;
    g_dh[cur^1][bk] = g_go[bk]*tanhf(dcn);
}

// X cols 0..2047 = [h | hb | ha | sw_h] fp16; also cb, ca, swc (fp32)
__global__ void k_build(const int* __restrict__ pos) {
    int n = blockIdx.x, k = threadIdx.x;
    int b = n >> 9, s = n & 511;
    size_t base = ((size_t)n << 9) + k;
    float hv = g_h[base];
    float hb = (s >= 1 ? g_h[base-512] : 0.f) + (s >= 2 ? g_h[base-1024] : 0.f);
    float ha = (s <= 510 ? g_h[base+512] : 0.f) + (s <= 509 ? g_h[base+1024] : 0.f);
    int p = pos[n];
    float sh = 0.f, sc = 0.f;
    if (p > 0) {
        size_t pb = ((size_t)((b<<9) + p - 1) << 9) + k;
        sh = g_h[pb]; sc = g_c[pb];
    }
    size_t xb = (size_t)n*KXT + k;
    g_XA[xb]        = __float2half_rn(hv);
    g_XA[xb + 512]  = __float2half_rn(hb);
    g_XA[xb + 1024] = __float2half_rn(ha);
    g_XA[xb + 1536] = __float2half_rn(sh);
    g_cb[base]  = (s >= 1 ? g_c[base-512] : 0.f) + (s >= 2 ? g_c[base-1024] : 0.f);
    g_ca[base]  = (s <= 510 ? g_c[base+512] : 0.f) + (s <= 509 ? g_c[base+1024] : 0.f);
    g_swc[base] = sc;
}

// ---------------- host ----------------
extern "C" void kernel_launch(void* const* d_in, const int* in_sizes, int n_in,
                              void* d_out, int out_size) {
    const float* word = (const float*)d_in[0];
    const float* ih   = (const float*)d_in[1];
    const float* icc  = (const float*)d_in[2];
    const float* Wx   = (const float*)d_in[3];
    const float* Wh   = (const float*)d_in[4];
    const float* Wi   = (const float*)d_in[5];
    const float* Wd   = (const float*)d_in[6];
    const float* Ws   = (const float*)d_in[7];
    const float* bias = (const float*)d_in[8];
    const float* gW   = (const float*)d_in[9];
    const float* gb   = (const float*)d_in[10];
    const int*   pos  = (const int*)d_in[11];
    const int*   mask = (const int*)d_in[12];
    float* out = (float*)d_out;

    cudaFuncSetAttribute(k_hgemm_big, cudaFuncAttributeMaxDynamicSharedMemorySize, SMEM_BYTES);
    cudaFuncSetAttribute(k_hgemm_gf,  cudaFuncAttributeMaxDynamicSharedMemorySize, SMEM_BYTES);

    // launches (2 harness launches precede): prep_init, meanhc, small, gf(<- ncu -s 5), ...
    k_prep_init<<<PREP_BLOCKS + INIT_BLOCKS, 256>>>(
        Wx, Wh, Wi, Ws, gW + (size_t)5*262144, word, ih, icc, mask);
    k_meanhc<<<dim3(Bb, 2), 512>>>();

    dim3 gbig(CN/BN, Nn/BM);   // (32, 128)
    dim3 ggf (Hh/BN, Nn/BM);   // (4, 128)
    int cur = 0;
    for (int layer = 0; layer < NLAYERS; layer++) {
        if (layer > 0) k_mean0<<<Bb, 512>>>();
        k_small<<<dim3(64, 11), 256>>>(gW, gb, Wd, cur, layer == 0);
        k_hgemm_gf<<<ggf, 256, SMEM_BYTES>>>(gb + 1024, mask);
        k_soft <<<Bb, 512>>>(cur);
        k_build<<<Nn, 512>>>(pos);
        k_hgemm_big<<<gbig, 256, SMEM_BYTES>>>(bias, mask, out, cur, layer == NLAYERS-1);
        cur ^= 1;
    }
}

// round 13
// speedup vs baseline: 3.0115x; 1.1720x over previous
#include <cuda_runtime.h>
#include <cuda_fp16.h>
#include <math.h>
#include <cstdint>

// Problem constants (fixed by reference setup_inputs)
#define Bb   32
#define Ss   512
#define Hh   512
#define Nn   (Bb*Ss)        // 16384 tokens
#define CN   4096           // 8 gates * H, interleaved c = k*8 + g
#define KXT  2560           // [h | hb | ha | sw_h | emb]
#define NLAYERS 4

// HMMA GEMM: 256x128 tile, 512 threads (16 warps, 8x2), BK=64, 2-term
#define BM 256
#define BN 128
#define BK 64
#define AROW 72                        // BK + 8 pad (halves); 144 bytes/row
#define A_BYTES  (BM*AROW*2)           // 36864
#define B_BYTES  (BN*AROW*2)           // 18432 per plane
#define A_OFF  0
#define BH_OFF A_BYTES
#define BL_OFF (A_BYTES + B_BYTES)
#define STAGE_BYTES (A_BYTES + 2*B_BYTES)  // 73728
#define NSTG 3
#define SMEM_BYTES (NSTG*STAGE_BYTES)  // 221184 <= 227KB; zs 256*132*4=135168 fits

// ---------------- device scratch ----------------
__device__ __half g_XA [(size_t)Nn*KXT];   // A single fp16
__device__ __half g_WH [(size_t)CN*KXT];   // B hi plane [c][j]
__device__ __half g_WL [(size_t)CN*KXT];   // B lo plane
__device__ __half g_GH [(size_t)Hh*Hh];    // gWhf hi [c][j]
__device__ __half g_GL [(size_t)Hh*Hh];    // gWhf lo
__device__ __half g_hA [(size_t)Nn*Hh];    // h fp16 (gf GEMM A)
__device__ float g_h  [(size_t)Nn*Hh];
__device__ float g_c  [(size_t)Nn*Hh];
__device__ float g_cb [(size_t)Nn*Hh];
__device__ float g_ca [(size_t)Nn*Hh];
__device__ float g_swc[(size_t)Nn*Hh];
__device__ float g_gf [(size_t)Nn*Hh];
__device__ float g_zd [Bb*CN];
__device__ float g_dh [2][Bb*Hh];
__device__ float g_dc [2][Bb*Hh];
__device__ float g_comb[Bb*Hh];
__device__ float g_gd [Bb*Hh];
__device__ float g_go [Bb*Hh];
__device__ float g_gfx[Bb*Hh];

__device__ __forceinline__ float sigm(float x) { return 1.f/(1.f+__expf(-x)); }
__device__ __forceinline__ void split2h(float v, __half& hi, __half& lo) {
    hi = __float2half_rn(v);
    lo = __float2half_rn(v - __half2float(hi));
}

__device__ __forceinline__ uint32_t smem_u32(const void* p) {
    uint32_t a;
    asm("{ .reg .u64 t; cvta.to.shared.u64 t, %1; cvt.u32.u64 %0, t; }" : "=r"(a) : "l"(p));
    return a;
}
__device__ __forceinline__ void mma16816(float* c, const uint32_t* a, uint32_t b0, uint32_t b1) {
    asm volatile("mma.sync.aligned.m16n8k16.row.col.f32.f16.f16.f32 "
        "{%0,%1,%2,%3},{%4,%5,%6,%7},{%8,%9},{%0,%1,%2,%3};"
        : "+f"(c[0]), "+f"(c[1]), "+f"(c[2]), "+f"(c[3])
        : "r"(a[0]), "r"(a[1]), "r"(a[2]), "r"(a[3]), "r"(b0), "r"(b1));
}
#define LDSM_X4(r, addr) \
    asm volatile("ldmatrix.sync.aligned.m8n8.x4.shared.b16 {%0,%1,%2,%3},[%4];" \
        : "=r"((r)[0]), "=r"((r)[1]), "=r"((r)[2]), "=r"((r)[3]) : "r"(addr))
#define CP_ASYNC(dst, src) \
    asm volatile("cp.async.cg.shared.global [%0],[%1],16;" :: "r"(dst), "l"(src))
#define CP_COMMIT() asm volatile("cp.async.commit_group;")

// ---------------- 2-term HMMA mainloop: C[256x128], BK=64, 3 stages ----------------
template<int KCHUNKS>
__device__ __forceinline__ void hmma_mainloop(
    const __half* __restrict__ AAp, int lda,
    const __half* __restrict__ BHp, const __half* __restrict__ BLp, int ldb,
    int n0, int c0, char* smem, float acc[2][8][4])
{
    const int tid = threadIdx.x, lane = tid & 31, wid = tid >> 5;
    const int wm = wid >> 1, wn = wid & 1;          // 8x2 warps, warp tile 32x64
    const uint32_t sb = smem_u32(smem);

    const uint32_t a_off0 = (uint32_t)(((wm*32 + (lane & 15))*AROW + (lane >> 4)*8) * 2);
    const uint32_t a_off1 = a_off0 + 16*AROW*2;
    const uint32_t b_off  = (uint32_t)(((wn*64 + ((lane >> 4) << 3) + (lane & 7))*AROW
                                        + ((lane >> 3) & 1)*8) * 2);

    auto issue = [&](int t) {
        const uint32_t base = sb + (t % NSTG)*STAGE_BYTES;
        #pragma unroll
        for (int i = 0; i < 4; i++) {               // A: 2048 segs
            const int q = tid + i*512;
            const int row = q >> 3, seg = q & 7;
            const uint32_t off = (uint32_t)((row*AROW + seg*8)*2);
            CP_ASYNC(base + A_OFF + off, AAp + (size_t)(n0+row)*lda + t*BK + seg*8);
        }
        #pragma unroll
        for (int i = 0; i < 2; i++) {               // B: 1024 segs per plane
            const int q = tid + i*512;
            const int row = q >> 3, seg = q & 7;
            const uint32_t off = (uint32_t)((row*AROW + seg*8)*2);
            const size_t gsrcB = (size_t)(c0+row)*ldb + t*BK + seg*8;
            CP_ASYNC(base + BH_OFF + off, BHp + gsrcB);
            CP_ASYNC(base + BL_OFF + off, BLp + gsrcB);
        }
        CP_COMMIT();
    };

    issue(0); issue(1);
    #pragma unroll 1
    for (int t = 0; t < KCHUNKS; t++) {
        if (t + 2 < KCHUNKS) asm volatile("cp.async.wait_group 1;");
        else                 asm volatile("cp.async.wait_group 0;");
        __syncthreads();
        if (t + 2 < KCHUNKS) issue(t + 2);          // stage (t-1)%3: safe post-barrier
        const uint32_t base = sb + (t % NSTG)*STAGE_BYTES;
        #pragma unroll
        for (int ks = 0; ks < 4; ks++) {
            const uint32_t kb = (uint32_t)(ks*32);  // 16 halves per k-step
            uint32_t Ahf[2][4];
            LDSM_X4(Ahf[0], base + A_OFF + a_off0 + kb);
            LDSM_X4(Ahf[1], base + A_OFF + a_off1 + kb);
            #pragma unroll
            for (int bp = 0; bp < 4; bp++) {
                uint32_t Bhf[4], Blf[4];
                LDSM_X4(Bhf, base + BH_OFF + b_off + bp*16*AROW*2 + kb);
                LDSM_X4(Blf, base + BL_OFF + b_off + bp*16*AROW*2 + kb);
                #pragma unroll
                for (int am = 0; am < 2; am++) {
                    mma16816(acc[am][2*bp],   Ahf[am], Bhf[0], Bhf[1]);
                    mma16816(acc[am][2*bp+1], Ahf[am], Bhf[2], Bhf[3]);
                    mma16816(acc[am][2*bp],   Ahf[am], Blf[0], Blf[1]);
                    mma16816(acc[am][2*bp+1], Ahf[am], Blf[2], Blf[3]);
                }
            }
        }
    }
}

// ---------------- big GEMM + fused SLSTM epilogue ----------------
__global__ void __launch_bounds__(512) k_hgemm_big(
    const float* __restrict__ bias, const int* __restrict__ mask,
    float* __restrict__ out, int cur, int last)
{
    extern __shared__ char smem[];
    const int n0 = blockIdx.y*BM, c0 = blockIdx.x*BN;
    float acc[2][8][4] = {};
    hmma_mainloop<KXT/BK>(g_XA, KXT, g_WH, g_WL, KXT, n0, c0, smem, acc);

    // stage z to smem (row stride 132 floats, 256 rows)
    float* zs = (float*)smem;
    const int lane = threadIdx.x & 31, wid = threadIdx.x >> 5;
    const int wm = wid >> 1, wn = wid & 1;
    const int g = lane >> 2, tg2 = (lane & 3)*2;
    __syncthreads();
    #pragma unroll
    for (int am = 0; am < 2; am++) {
        const int ra = wm*32 + am*16 + g;
        #pragma unroll
        for (int na = 0; na < 8; na++) {
            const int col = wn*64 + na*8 + tg2;
            *(float2*)&zs[ra*132 + col]     = *(float2*)&acc[am][na][0];
            *(float2*)&zs[(ra+8)*132 + col] = *(float2*)&acc[am][na][2];
        }
    }
    __syncthreads();

    // per-unit epilogue: 16 units x 256 rows in this tile
    const int u = threadIdx.x & 15, rgrp = threadIdx.x >> 4;   // 32 rgrps x 8 rows
    const int kout = (c0 >> 3) + u;
    const float* dc_old = g_dc[cur];
    float* hout = last ? out : g_h;
    float bz[8];
    #pragma unroll
    for (int gg = 0; gg < 8; gg++) bz[gg] = bias[gg*512 + kout];

    #pragma unroll 1
    for (int i = 0; i < 8; i++) {
        const int n = n0 + rgrp*8 + i;
        const int b = n >> 9;
        const float m = (float)mask[n];
        float z[8];
        *(float4*)&z[0] = *(float4*)&zs[(rgrp*8+i)*132 + u*8];
        *(float4*)&z[4] = *(float4*)&zs[(rgrp*8+i)*132 + u*8 + 4];
        #pragma unroll
        for (int gg = 0; gg < 8; gg++)
            z[gg] += g_zd[(b<<12)+(kout<<3)+gg] + bz[gg];
        float e[6], ssum = 0.f;
        #pragma unroll
        for (int j = 0; j < 6; j++) { e[j] = __expf(sigm(z[j])); ssum += e[j]; }
        const float inv = 1.f/ssum;
        const float o = sigm(z[6]);
        const float u_t = tanhf(z[7]);
        const size_t idx = ((size_t)n << 9) + kout;
        float cn = (e[0]*g_cb[idx] + e[1]*g_ca[idx] + e[2]*g_c[idx]
                  + e[3]*dc_old[(b<<9)+kout] + e[4]*g_swc[idx] + e[5]*u_t) * inv;
        cn *= m;
        const float hv = o * tanhf(cn) * m;
        hout[idx] = hv;
        g_c[idx]  = cn;
        g_hA[idx] = __float2half_rn(hv);
    }
}

// ---------------- gf GEMM: gf = sigmoid(h @ gWhf + gfx + gbf) + mask_score ----------------
__global__ void __launch_bounds__(512) k_hgemm_gf(
    const float* __restrict__ gbf, const int* __restrict__ mask)
{
    extern __shared__ char smem[];
    const int n0 = blockIdx.y*BM, c0 = blockIdx.x*BN;
    float acc[2][8][4] = {};
    hmma_mainloop<Hh/BK>(g_hA, Hh, g_GH, g_GL, Hh, n0, c0, smem, acc);

    const int lane = threadIdx.x & 31, wid = threadIdx.x >> 5;
    const int wm = wid >> 1, wn = wid & 1;
    const int g = lane >> 2, tg2 = (lane & 3)*2;
    #pragma unroll
    for (int am = 0; am < 2; am++) {
        #pragma unroll
        for (int half = 0; half < 2; half++) {
            const int n = n0 + wm*32 + am*16 + g + half*8;
            const int b = n >> 9;
            const float ms = mask[n] ? 0.f : -1e25f;
            #pragma unroll
            for (int na = 0; na < 8; na++) {
                const int cc = c0 + wn*64 + na*8 + tg2;
                float2 r;
                r.x = sigm(acc[am][na][half*2+0] + g_gfx[(b<<9)+cc]   + gbf[cc])   + ms;
                r.y = sigm(acc[am][na][half*2+1] + g_gfx[(b<<9)+cc+1] + gbf[cc+1]) + ms;
                *(float2*)&g_gf[((size_t)n<<9) + cc] = r;
            }
        }
    }
}

// ---------------- one-time prep (weights) + init (inputs), merged ----------------
#define PREP_ELEMS ((size_t)CN*KXT + (size_t)Hh*Hh)
#define PREP_BLOCKS ((int)(PREP_ELEMS/256))          // 41984
#define INIT_BLOCKS ((Nn*Hh)/256)                    // 32768
__global__ void k_prep_init(
    const float* __restrict__ Wx, const float* __restrict__ Wh,
    const float* __restrict__ Wi, const float* __restrict__ Ws,
    const float* __restrict__ gWhf,
    const float* __restrict__ word, const float* __restrict__ ih,
    const float* __restrict__ icc, const int* __restrict__ mask)
{
    if (blockIdx.x < PREP_BLOCKS) {
        size_t idx = (size_t)blockIdx.x*256 + threadIdx.x;
        if (idx < (size_t)CN*KXT) {
            int c = (int)(idx / KXT), j = (int)(idx % KXT);
            int g = c & 7, k = c >> 3;
            float v;
            if (j < 512)        v = Wx[((size_t)((g<<9)  + j       ))*512 + k];
            else if (j < 1536)  v = Wh[((size_t)((g<<10) + (j-512) ))*512 + k];
            else if (j < 2048)  v = Ws[((size_t)((g<<9)  + (j-1536)))*512 + k];
            else                v = Wi[((size_t)((g<<9)  + (j-2048)))*512 + k];
            split2h(v, g_WH[idx], g_WL[idx]);
        } else {
            int r = (int)(idx - (size_t)CN*KXT);     // < 512*512
            int kcol = r >> 9, j = r & 511;
            split2h(gWhf[j*512 + kcol], g_GH[r], g_GL[r]);
        }
    } else {
        size_t idx = (size_t)(blockIdx.x - PREP_BLOCKS)*256 + threadIdx.x;  // < Nn*512
        int n = (int)(idx >> 9), k = (int)(idx & 511);
        float m = (float)mask[n];
        float hv = ih[idx]*m;
        g_h[idx]  = hv;
        g_hA[idx] = __float2half_rn(hv);
        g_c[idx]  = icc[idx]*m;
        g_XA[(size_t)n*KXT + 2048 + k] = __float2half_rn(word[idx]*m);
    }
}

// mean(h)->dh[0] (y=0) and mean(c)->dc[0] (y=1), 4-way unrolled for MLP
__global__ void k_meanhc() {
    int b = blockIdx.x, k = threadIdx.x;
    const float* x = (blockIdx.y ? g_c : g_h) + ((size_t)(b<<9))*512 + k;
    float s0=0.f, s1=0.f, s2=0.f, s3=0.f;
    for (int t = 0; t < Ss; t += 4) {
        s0 += x[(size_t)t*512];       s1 += x[(size_t)(t+1)*512];
        s2 += x[(size_t)(t+2)*512];   s3 += x[(size_t)(t+3)*512];
    }
    float s = ((s0+s1)+(s2+s3)) * (1.f/512.f);
    int o = (b<<9) + k;
    if (blockIdx.y) g_dc[0][o] = s; else g_dh[0][o] = s;
}

// mean(h)->comb (layers >= 1)
__global__ void k_mean0() {
    int b = blockIdx.x, k = threadIdx.x;
    const float* x = g_h + ((size_t)(b<<9))*512 + k;
    float s0=0.f, s1=0.f, s2=0.f, s3=0.f;
    for (int t = 0; t < Ss; t += 4) {
        s0 += x[(size_t)t*512];       s1 += x[(size_t)(t+1)*512];
        s2 += x[(size_t)(t+2)*512];   s3 += x[(size_t)(t+3)*512];
    }
    g_comb[(b<<9) + k] = ((s0+s1)+(s2+s3)) * (1.f/512.f);
}

// small per-batch GEMMs: gd, go, gfx, zd[g]. layer0: comb == dh[0]
__global__ void k_small(const float* __restrict__ gW, const float* __restrict__ gb,
                        const float* __restrict__ Wd, int cur, int layer0) {
    int t = blockIdx.y;
    int idx = blockIdx.x*256 + threadIdx.x;   // 0..16383 = (b,k)
    int b = idx >> 9, k = idx & 511;
    const float* dh = g_dh[cur] + (b<<9);
    float s = 0.f;
    if (t <= 1) {
        const float* W1 = gW + (size_t)(t*2  )*262144;
        const float* W2 = gW + (size_t)(t*2+1)*262144;
        const float* cm = (layer0 ? g_dh[cur] : g_comb) + (b<<9);
        for (int j = 0; j < 512; j++)
            s = fmaf(dh[j], W1[j*512+k], fmaf(cm[j], W2[j*512+k], s));
        float v = sigm(s + gb[t*512 + k]);
        if (t == 0) g_gd[idx] = v; else g_go[idx] = v;
    } else if (t == 2) {
        const float* W = gW + (size_t)4*262144;   // gWxf
        for (int j = 0; j < 512; j++) s = fmaf(dh[j], W[j*512+k], s);
        g_gfx[idx] = s;
    } else {
        int g = t - 3;
        const float* W = Wd + (size_t)g*262144;
        for (int j = 0; j < 512; j++) s = fmaf(dh[j], W[j*512+k], s);
        g_zd[(b<<12) + (k<<3) + g] = s;
    }
}

// softmax over S+1 entries per (b,k) + new dummies
__global__ void k_soft(int cur) {
    int b = blockIdx.x, k = threadIdx.x;
    int bk = (b<<9) + k;
    float den = __expf(g_gd[bk] - 1.f);
    float num = den * g_dc[cur][bk];
    const float* gf = g_gf + (size_t)b*Ss*Hh + k;
    const float* cp = g_c  + (size_t)b*Ss*Hh + k;
    for (int s = 0; s < Ss; s++) {
        float w = __expf(gf[s*512] - 1.f);
        num = fmaf(w, cp[s*512], num);
        den += w;
    }
    float dcn = num/den;
    g_dc[cur^1][bk] = dcn;
    g_dh[cur^1][bk] = g_go[bk]*tanhf(dcn);
}

// X cols 0..2047 = [h | hb | ha | sw_h] fp16; also cb, ca, swc (fp32)
__global__ void k_build(const int* __restrict__ pos) {
    int n = blockIdx.x, k = threadIdx.x;
    int b = n >> 9, s = n & 511;
    size_t base = ((size_t)n << 9) + k;
    float hv = g_h[base];
    float hb = (s >= 1 ? g_h[base-512] : 0.f) + (s >= 2 ? g_h[base-1024] : 0.f);
    float ha = (s <= 510 ? g_h[base+512] : 0.f) + (s <= 509 ? g_h[base+1024] : 0.f);
    int p = pos[n];
    float sh = 0.f, sc = 0.f;
    if (p > 0) {
        size_t pb = ((size_t)((b<<9) + p - 1) << 9) + k;
        sh = g_h[pb]; sc = g_c[pb];
    }
    size_t xb = (size_t)n*KXT + k;
    g_XA[xb]        = __float2half_rn(hv);
    g_XA[xb + 512]  = __float2half_rn(hb);
    g_XA[xb + 1024] = __float2half_rn(ha);
    g_XA[xb + 1536] = __float2half_rn(sh);
    g_cb[base]  = (s >= 1 ? g_c[base-512] : 0.f) + (s >= 2 ? g_c[base-1024] : 0.f);
    g_ca[base]  = (s <= 510 ? g_c[base+512] : 0.f) + (s <= 509 ? g_c[base+1024] : 0.f);
    g_swc[base] = sc;
}

// ---------------- host ----------------
extern "C" void kernel_launch(void* const* d_in, const int* in_sizes, int n_in,
                              void* d_out, int out_size) {
    const float* word = (const float*)d_in[0];
    const float* ih   = (const float*)d_in[1];
    const float* icc  = (const float*)d_in[2];
    const float* Wx   = (const float*)d_in[3];
    const float* Wh   = (const float*)d_in[4];
    const float* Wi   = (const float*)d_in[5];
    const float* Wd   = (const float*)d_in[6];
    const float* Ws   = (const float*)d_in[7];
    const float* bias = (const float*)d_in[8];
    const float* gW   = (const float*)d_in[9];
    const float* gb   = (const float*)d_in[10];
    const int*   pos  = (const int*)d_in[11];
    const int*   mask = (const int*)d_in[12];
    float* out = (float*)d_out;

    cudaFuncSetAttribute(k_hgemm_big, cudaFuncAttributeMaxDynamicSharedMemorySize, SMEM_BYTES);
    cudaFuncSetAttribute(k_hgemm_gf,  cudaFuncAttributeMaxDynamicSharedMemorySize, SMEM_BYTES);

    k_prep_init<<<PREP_BLOCKS + INIT_BLOCKS, 256>>>(
        Wx, Wh, Wi, Ws, gW + (size_t)5*262144, word, ih, icc, mask);
    k_meanhc<<<dim3(Bb, 2), 512>>>();

    dim3 gbig(CN/BN, Nn/BM);   // (32, 64)
    dim3 ggf (Hh/BN, Nn/BM);   // (4, 64)
    int cur = 0;
    for (int layer = 0; layer < NLAYERS; layer++) {
        if (layer > 0) k_mean0<<<Bb, 512>>>();
        k_small<<<dim3(64, 11), 256>>>(gW, gb, Wd, cur, layer == 0);
        k_hgemm_gf<<<ggf, 512, SMEM_BYTES>>>(gb + 1024, mask);
        k_soft <<<Bb, 512>>>(cur);
        k_build<<<Nn, 512>>>(pos);
        k_hgemm_big<<<gbig, 512, SMEM_BYTES>>>(bias, mask, out, cur, layer == NLAYERS-1);
        cur ^= 1;
    }
}

// round 14
// speedup vs baseline: 4.2066x; 1.3968x over previous
#include <cuda_runtime.h>
#include <cuda_fp16.h>
#include <math.h>
#include <cstdint>

// Problem constants (fixed by reference setup_inputs)
#define Bb   32
#define Ss   512
#define Hh   512
#define Nn   (Bb*Ss)        // 16384 tokens
#define CN   4096           // 8 gates * H, interleaved c = k*8 + g
#define KXT  2560           // [h | hb | ha | sw_h | emb]
#define NLAYERS 4

// HMMA GEMM: 256x128 tile, 512 threads (16 warps, 8x2), BK=64
// big GEMM: A fp16 x B fp16 (1-term, 4 stages). gf GEMM: B split hi/lo (2-term, 3 stages).
#define BM 256
#define BN 128
#define BK 64
#define AROW 72                        // BK + 8 pad (halves); 144 bytes/row
#define A_BYTES  (BM*AROW*2)           // 36864
#define B_BYTES  (BN*AROW*2)           // 18432 per plane
#define SMEM_BYTES 221184              // = 4*(A+B) = 3*(A+2B); zs 256*132*4=135168 fits

// ---------------- device scratch ----------------
__device__ __half g_XA [(size_t)Nn*KXT];   // A single fp16
__device__ __half g_WH [(size_t)CN*KXT];   // W fp16 [c][j]
__device__ __half g_GH [(size_t)Hh*Hh];    // gWhf hi [c][j]
__device__ __half g_GL [(size_t)Hh*Hh];    // gWhf lo
__device__ __half g_hA [(size_t)Nn*Hh];    // h fp16 (gf GEMM A)
__device__ float g_h  [(size_t)Nn*Hh];
__device__ float g_c  [(size_t)Nn*Hh];
__device__ float g_cb [(size_t)Nn*Hh];
__device__ float g_ca [(size_t)Nn*Hh];
__device__ float g_swc[(size_t)Nn*Hh];
__device__ float g_gf [(size_t)Nn*Hh];
__device__ float g_zd [Bb*CN];
__device__ float g_dh [2][Bb*Hh];
__device__ float g_dc [2][Bb*Hh];
__device__ float g_comb[Bb*Hh];
__device__ float g_gd [Bb*Hh];
__device__ float g_go [Bb*Hh];
__device__ float g_gfx[Bb*Hh];

__device__ __forceinline__ float sigm(float x) { return 1.f/(1.f+__expf(-x)); }
__device__ __forceinline__ void split2h(float v, __half& hi, __half& lo) {
    hi = __float2half_rn(v);
    lo = __float2half_rn(v - __half2float(hi));
}

__device__ __forceinline__ uint32_t smem_u32(const void* p) {
    uint32_t a;
    asm("{ .reg .u64 t; cvta.to.shared.u64 t, %1; cvt.u32.u64 %0, t; }" : "=r"(a) : "l"(p));
    return a;
}
__device__ __forceinline__ void mma16816(float* c, const uint32_t* a, uint32_t b0, uint32_t b1) {
    asm volatile("mma.sync.aligned.m16n8k16.row.col.f32.f16.f16.f32 "
        "{%0,%1,%2,%3},{%4,%5,%6,%7},{%8,%9},{%0,%1,%2,%3};"
        : "+f"(c[0]), "+f"(c[1]), "+f"(c[2]), "+f"(c[3])
        : "r"(a[0]), "r"(a[1]), "r"(a[2]), "r"(a[3]), "r"(b0), "r"(b1));
}
#define LDSM_X4(r, addr) \
    asm volatile("ldmatrix.sync.aligned.m8n8.x4.shared.b16 {%0,%1,%2,%3},[%4];" \
        : "=r"((r)[0]), "=r"((r)[1]), "=r"((r)[2]), "=r"((r)[3]) : "r"(addr))
#define CP_ASYNC(dst, src) \
    asm volatile("cp.async.cg.shared.global [%0],[%1],16;" :: "r"(dst), "l"(src))
#define CP_COMMIT() asm volatile("cp.async.commit_group;")

// ---------------- HMMA mainloop: C[256x128], BK=64, templated B-split ----------------
template<int KCHUNKS, int NST, bool SPLITB>
__device__ __forceinline__ void hmma_mainloop(
    const __half* __restrict__ AAp, int lda,
    const __half* __restrict__ BHp, const __half* __restrict__ BLp, int ldb,
    int n0, int c0, char* smem, float acc[2][8][4])
{
    constexpr int STG = A_BYTES + (SPLITB ? 2 : 1)*B_BYTES;
    constexpr uint32_t BH_OFF = A_BYTES;
    constexpr uint32_t BL_OFF = A_BYTES + B_BYTES;
    const int tid = threadIdx.x, lane = tid & 31, wid = tid >> 5;
    const int wm = wid >> 1, wn = wid & 1;          // 8x2 warps, warp tile 32x64
    const uint32_t sb = smem_u32(smem);

    const uint32_t a_off0 = (uint32_t)(((wm*32 + (lane & 15))*AROW + (lane >> 4)*8) * 2);
    const uint32_t a_off1 = a_off0 + 16*AROW*2;
    const uint32_t b_off  = (uint32_t)(((wn*64 + ((lane >> 4) << 3) + (lane & 7))*AROW
                                        + ((lane >> 3) & 1)*8) * 2);

    auto issue = [&](int t) {
        const uint32_t base = sb + (t % NST)*STG;
        #pragma unroll
        for (int i = 0; i < 4; i++) {               // A: 2048 segs
            const int q = tid + i*512;
            const int row = q >> 3, seg = q & 7;
            const uint32_t off = (uint32_t)((row*AROW + seg*8)*2);
            CP_ASYNC(base + off, AAp + (size_t)(n0+row)*lda + t*BK + seg*8);
        }
        #pragma unroll
        for (int i = 0; i < 2; i++) {               // B: 1024 segs per plane
            const int q = tid + i*512;
            const int row = q >> 3, seg = q & 7;
            const uint32_t off = (uint32_t)((row*AROW + seg*8)*2);
            const size_t gsrcB = (size_t)(c0+row)*ldb + t*BK + seg*8;
            CP_ASYNC(base + BH_OFF + off, BHp + gsrcB);
            if (SPLITB) CP_ASYNC(base + BL_OFF + off, BLp + gsrcB);
        }
        CP_COMMIT();
    };

    #pragma unroll
    for (int i = 0; i < NST-1; i++) issue(i);
    #pragma unroll 1
    for (int t = 0; t < KCHUNKS; t++) {
        if (NST >= 4 && t + 3 <= KCHUNKS) asm volatile("cp.async.wait_group 2;");
        else if (t + 2 <= KCHUNKS)        asm volatile("cp.async.wait_group 1;");
        else                              asm volatile("cp.async.wait_group 0;");
        __syncthreads();
        if (t + NST - 1 < KCHUNKS) issue(t + NST - 1);   // stage (t-1)%NST: safe post-barrier
        const uint32_t base = sb + (t % NST)*STG;
        #pragma unroll
        for (int ks = 0; ks < 4; ks++) {
            const uint32_t kb = (uint32_t)(ks*32);  // 16 halves per k-step
            uint32_t Ahf[2][4];
            LDSM_X4(Ahf[0], base + a_off0 + kb);
            LDSM_X4(Ahf[1], base + a_off1 + kb);
            #pragma unroll
            for (int bp = 0; bp < 4; bp++) {
                uint32_t Bhf[4];
                LDSM_X4(Bhf, base + BH_OFF + b_off + bp*16*AROW*2 + kb);
                #pragma unroll
                for (int am = 0; am < 2; am++) {
                    mma16816(acc[am][2*bp],   Ahf[am], Bhf[0], Bhf[1]);
                    mma16816(acc[am][2*bp+1], Ahf[am], Bhf[2], Bhf[3]);
                }
                if (SPLITB) {
                    uint32_t Blf[4];
                    LDSM_X4(Blf, base + BL_OFF + b_off + bp*16*AROW*2 + kb);
                    #pragma unroll
                    for (int am = 0; am < 2; am++) {
                        mma16816(acc[am][2*bp],   Ahf[am], Blf[0], Blf[1]);
                        mma16816(acc[am][2*bp+1], Ahf[am], Blf[2], Blf[3]);
                    }
                }
            }
        }
    }
}

// ---------------- big GEMM + fused SLSTM epilogue ----------------
__global__ void __launch_bounds__(512) k_hgemm_big(
    const float* __restrict__ bias, const int* __restrict__ mask,
    float* __restrict__ out, int cur, int last)
{
    extern __shared__ char smem[];
    const int n0 = blockIdx.y*BM, c0 = blockIdx.x*BN;
    float acc[2][8][4] = {};
    hmma_mainloop<KXT/BK, 4, false>(g_XA, KXT, g_WH, nullptr, KXT, n0, c0, smem, acc);

    // stage z to smem (row stride 132 floats, 256 rows)
    float* zs = (float*)smem;
    const int lane = threadIdx.x & 31, wid = threadIdx.x >> 5;
    const int wm = wid >> 1, wn = wid & 1;
    const int g = lane >> 2, tg2 = (lane & 3)*2;
    __syncthreads();
    #pragma unroll
    for (int am = 0; am < 2; am++) {
        const int ra = wm*32 + am*16 + g;
        #pragma unroll
        for (int na = 0; na < 8; na++) {
            const int col = wn*64 + na*8 + tg2;
            *(float2*)&zs[ra*132 + col]     = *(float2*)&acc[am][na][0];
            *(float2*)&zs[(ra+8)*132 + col] = *(float2*)&acc[am][na][2];
        }
    }
    __syncthreads();

    // per-unit epilogue: 16 units x 256 rows in this tile
    const int u = threadIdx.x & 15, rgrp = threadIdx.x >> 4;   // 32 rgrps x 8 rows
    const int kout = (c0 >> 3) + u;
    const float* dc_old = g_dc[cur];
    float* hout = last ? out : g_h;
    float bz[8];
    #pragma unroll
    for (int gg = 0; gg < 8; gg++) bz[gg] = bias[gg*512 + kout];

    #pragma unroll 1
    for (int i = 0; i < 8; i++) {
        const int n = n0 + rgrp*8 + i;
        const int b = n >> 9;
        const float m = (float)mask[n];
        float z[8];
        *(float4*)&z[0] = *(float4*)&zs[(rgrp*8+i)*132 + u*8];
        *(float4*)&z[4] = *(float4*)&zs[(rgrp*8+i)*132 + u*8 + 4];
        #pragma unroll
        for (int gg = 0; gg < 8; gg++)
            z[gg] += g_zd[(b<<12)+(kout<<3)+gg] + bz[gg];
        float e[6], ssum = 0.f;
        #pragma unroll
        for (int j = 0; j < 6; j++) { e[j] = __expf(sigm(z[j])); ssum += e[j]; }
        const float inv = 1.f/ssum;
        const float o = sigm(z[6]);
        const float u_t = tanhf(z[7]);
        const size_t idx = ((size_t)n << 9) + kout;
        float cn = (e[0]*g_cb[idx] + e[1]*g_ca[idx] + e[2]*g_c[idx]
                  + e[3]*dc_old[(b<<9)+kout] + e[4]*g_swc[idx] + e[5]*u_t) * inv;
        cn *= m;
        const float hv = o * tanhf(cn) * m;
        hout[idx] = hv;
        g_c[idx]  = cn;
        g_hA[idx] = __float2half_rn(hv);
    }
}

// ---------------- gf GEMM: gf = sigmoid(h @ gWhf + gfx + gbf) + mask_score ----------------
__global__ void __launch_bounds__(512) k_hgemm_gf(
    const float* __restrict__ gbf, const int* __restrict__ mask)
{
    extern __shared__ char smem[];
    const int n0 = blockIdx.y*BM, c0 = blockIdx.x*BN;
    float acc[2][8][4] = {};
    hmma_mainloop<Hh/BK, 3, true>(g_hA, Hh, g_GH, g_GL, Hh, n0, c0, smem, acc);

    const int lane = threadIdx.x & 31, wid = threadIdx.x >> 5;
    const int wm = wid >> 1, wn = wid & 1;
    const int g = lane >> 2, tg2 = (lane & 3)*2;
    #pragma unroll
    for (int am = 0; am < 2; am++) {
        #pragma unroll
        for (int half = 0; half < 2; half++) {
            const int n = n0 + wm*32 + am*16 + g + half*8;
            const int b = n >> 9;
            const float ms = mask[n] ? 0.f : -1e25f;
            #pragma unroll
            for (int na = 0; na < 8; na++) {
                const int cc = c0 + wn*64 + na*8 + tg2;
                float2 r;
                r.x = sigm(acc[am][na][half*2+0] + g_gfx[(b<<9)+cc]   + gbf[cc])   + ms;
                r.y = sigm(acc[am][na][half*2+1] + g_gfx[(b<<9)+cc+1] + gbf[cc+1]) + ms;
                *(float2*)&g_gf[((size_t)n<<9) + cc] = r;
            }
        }
    }
}

// ---------------- one-time prep (weights) + init (inputs), merged ----------------
#define PREP_ELEMS ((size_t)CN*KXT + (size_t)Hh*Hh)
#define PREP_BLOCKS ((int)(PREP_ELEMS/256))          // 41984
#define INIT_BLOCKS ((Nn*Hh)/256)                    // 32768
__global__ void k_prep_init(
    const float* __restrict__ Wx, const float* __restrict__ Wh,
    const float* __restrict__ Wi, const float* __restrict__ Ws,
    const float* __restrict__ gWhf,
    const float* __restrict__ word, const float* __restrict__ ih,
    const float* __restrict__ icc, const int* __restrict__ mask)
{
    if (blockIdx.x < PREP_BLOCKS) {
        size_t idx = (size_t)blockIdx.x*256 + threadIdx.x;
        if (idx < (size_t)CN*KXT) {
            int c = (int)(idx / KXT), j = (int)(idx % KXT);
            int g = c & 7, k = c >> 3;
            float v;
            if (j < 512)        v = Wx[((size_t)((g<<9)  + j       ))*512 + k];
            else if (j < 1536)  v = Wh[((size_t)((g<<10) + (j-512) ))*512 + k];
            else if (j < 2048)  v = Ws[((size_t)((g<<9)  + (j-1536)))*512 + k];
            else                v = Wi[((size_t)((g<<9)  + (j-2048)))*512 + k];
            g_WH[idx] = __float2half_rn(v);
        } else {
            int r = (int)(idx - (size_t)CN*KXT);     // < 512*512
            int kcol = r >> 9, j = r & 511;
            split2h(gWhf[j*512 + kcol], g_GH[r], g_GL[r]);
        }
    } else {
        size_t idx = (size_t)(blockIdx.x - PREP_BLOCKS)*256 + threadIdx.x;  // < Nn*512
        int n = (int)(idx >> 9), k = (int)(idx & 511);
        float m = (float)mask[n];
        float hv = ih[idx]*m;
        g_h[idx]  = hv;
        g_hA[idx] = __float2half_rn(hv);
        g_c[idx]  = icc[idx]*m;
        g_XA[(size_t)n*KXT + 2048 + k] = __float2half_rn(word[idx]*m);
    }
}

// mean(h)->dh[0] (y=0) and mean(c)->dc[0] (y=1), 4-way unrolled for MLP
__global__ void k_meanhc() {
    int b = blockIdx.x, k = threadIdx.x;
    const float* x = (blockIdx.y ? g_c : g_h) + ((size_t)(b<<9))*512 + k;
    float s0=0.f, s1=0.f, s2=0.f, s3=0.f;
    for (int t = 0; t < Ss; t += 4) {
        s0 += x[(size_t)t*512];       s1 += x[(size_t)(t+1)*512];
        s2 += x[(size_t)(t+2)*512];   s3 += x[(size_t)(t+3)*512];
    }
    float s = ((s0+s1)+(s2+s3)) * (1.f/512.f);
    int o = (b<<9) + k;
    if (blockIdx.y) g_dc[0][o] = s; else g_dh[0][o] = s;
}

// mean(h)->comb (layers >= 1)
__global__ void k_mean0() {
    int b = blockIdx.x, k = threadIdx.x;
    const float* x = g_h + ((size_t)(b<<9))*512 + k;
    float s0=0.f, s1=0.f, s2=0.f, s3=0.f;
    for (int t = 0; t < Ss; t += 4) {
        s0 += x[(size_t)t*512];       s1 += x[(size_t)(t+1)*512];
        s2 += x[(size_t)(t+2)*512];   s3 += x[(size_t)(t+3)*512];
    }
    g_comb[(b<<9) + k] = ((s0+s1)+(s2+s3)) * (1.f/512.f);
}

// small per-batch GEMMs: gd, go, gfx, zd[g]. layer0: comb == dh[0]
__global__ void k_small(const float* __restrict__ gW, const float* __restrict__ gb,
                        const float* __restrict__ Wd, int cur, int layer0) {
    int t = blockIdx.y;
    int idx = blockIdx.x*256 + threadIdx.x;   // 0..16383 = (b,k)
    int b = idx >> 9, k = idx & 511;
    const float* dh = g_dh[cur] + (b<<9);
    float s = 0.f;
    if (t <= 1) {
        const float* W1 = gW + (size_t)(t*2  )*262144;
        const float* W2 = gW + (size_t)(t*2+1)*262144;
        const float* cm = (layer0 ? g_dh[cur] : g_comb) + (b<<9);
        for (int j = 0; j < 512; j++)
            s = fmaf(dh[j], W1[j*512+k], fmaf(cm[j], W2[j*512+k], s));
        float v = sigm(s + gb[t*512 + k]);
        if (t == 0) g_gd[idx] = v; else g_go[idx] = v;
    } else if (t == 2) {
        const float* W = gW + (size_t)4*262144;   // gWxf
        for (int j = 0; j < 512; j++) s = fmaf(dh[j], W[j*512+k], s);
        g_gfx[idx] = s;
    } else {
        int g = t - 3;
        const float* W = Wd + (size_t)g*262144;
        for (int j = 0; j < 512; j++) s = fmaf(dh[j], W[j*512+k], s);
        g_zd[(b<<12) + (k<<3) + g] = s;
    }
}

// softmax over S+1 entries per (b,k) + new dummies
__global__ void k_soft(int cur) {
    int b = blockIdx.x, k = threadIdx.x;
    int bk = (b<<9) + k;
    float den = __expf(g_gd[bk] - 1.f);
    float num = den * g_dc[cur][bk];
    const float* gf = g_gf + (size_t)b*Ss*Hh + k;
    const float* cp = g_c  + (size_t)b*Ss*Hh + k;
    for (int s = 0; s < Ss; s++) {
        float w = __expf(gf[s*512] - 1.f);
        num = fmaf(w, cp[s*512], num);
        den += w;
    }
    float dcn = num/den;
    g_dc[cur^1][bk] = dcn;
    g_dh[cur^1][bk] = g_go[bk]*tanhf(dcn);
}

// X cols 0..2047 = [h | hb | ha | sw_h] fp16; also cb, ca, swc (fp32)
__global__ void k_build(const int* __restrict__ pos) {
    int n = blockIdx.x, k = threadIdx.x;
    int b = n >> 9, s = n & 511;
    size_t base = ((size_t)n << 9) + k;
    float hv = g_h[base];
    float hb = (s >= 1 ? g_h[base-512] : 0.f) + (s >= 2 ? g_h[base-1024] : 0.f);
    float ha = (s <= 510 ? g_h[base+512] : 0.f) + (s <= 509 ? g_h[base+1024] : 0.f);
    int p = pos[n];
    float sh = 0.f, sc = 0.f;
    if (p > 0) {
        size_t pb = ((size_t)((b<<9) + p - 1) << 9) + k;
        sh = g_h[pb]; sc = g_c[pb];
    }
    size_t xb = (size_t)n*KXT + k;
    g_XA[xb]        = __float2half_rn(hv);
    g_XA[xb + 512]  = __float2half_rn(hb);
    g_XA[xb + 1024] = __float2half_rn(ha);
    g_XA[xb + 1536] = __float2half_rn(sh);
    g_cb[base]  = (s >= 1 ? g_c[base-512] : 0.f) + (s >= 2 ? g_c[base-1024] : 0.f);
    g_ca[base]  = (s <= 510 ? g_c[base+512] : 0.f) + (s <= 509 ? g_c[base+1024] : 0.f);
    g_swc[base] = sc;
}

// ---------------- host ----------------
extern "C" void kernel_launch(void* const* d_in, const int* in_sizes, int n_in,
                              void* d_out, int out_size) {
    const float* word = (const float*)d_in[0];
    const float* ih   = (const float*)d_in[1];
    const float* icc  = (const float*)d_in[2];
    const float* Wx   = (const float*)d_in[3];
    const float* Wh   = (const float*)d_in[4];
    const float* Wi   = (const float*)d_in[5];
    const float* Wd   = (const float*)d_in[6];
    const float* Ws   = (const float*)d_in[7];
    const float* bias = (const float*)d_in[8];
    const float* gW   = (const float*)d_in[9];
    const float* gb   = (const float*)d_in[10];
    const int*   pos  = (const int*)d_in[11];
    const int*   mask = (const int*)d_in[12];
    float* out = (float*)d_out;

    cudaFuncSetAttribute(k_hgemm_big, cudaFuncAttributeMaxDynamicSharedMemorySize, SMEM_BYTES);
    cudaFuncSetAttribute(k_hgemm_gf,  cudaFuncAttributeMaxDynamicSharedMemorySize, SMEM_BYTES);

    k_prep_init<<<PREP_BLOCKS + INIT_BLOCKS, 256>>>(
        Wx, Wh, Wi, Ws, gW + (size_t)5*262144, word, ih, icc, mask);
    k_meanhc<<<dim3(Bb, 2), 512>>>();

    dim3 gbig(CN/BN, Nn/BM);   // (32, 64)
    dim3 ggf (Hh/BN, Nn/BM);   // (4, 64)
    int cur = 0;
    for (int layer = 0; layer < NLAYERS; layer++) {
        if (layer > 0) k_mean0<<<Bb, 512>>>();
        k_small<<<dim3(64, 11), 256>>>(gW, gb, Wd, cur, layer == 0);
        k_hgemm_gf<<<ggf, 512, SMEM_BYTES>>>(gb + 1024, mask);
        k_soft <<<Bb, 512>>>(cur);
        k_build<<<Nn, 512>>>(pos);
        k_hgemm_big<<<gbig, 512, SMEM_BYTES>>>(bias, mask, out, cur, layer == NLAYERS-1);
        cur ^= 1;
    }
}